// round 7
// baseline (speedup 1.0000x reference)
#include <cuda_runtime.h>
#include <math.h>

#define Bb 16
#define Gg 512
#define Pp 512
#define Ee 256
#define Hh 16
#define Kd 16
#define HK 256

typedef unsigned long long ull;

// Scratch (device globals: allocation-free rule)
__device__ float g_c1[Bb * HK];
__device__ float g_Kt[Bb * Hh * Pp * Kd];   // [B,H,P,Kd]
__device__ float g_Vt[Bb * Hh * Pp * Kd];
__device__ float g_Qt[Bb * Hh * Gg * Kd];
__device__ float g_attn[Bb * Gg * HK];
__device__ float g_mh[Bb * Gg * HK];

// ---- packed f32x2 helpers ---------------------------------------------------
__device__ __forceinline__ ull dup2(float a) {
    ull r; asm("mov.b64 %0, {%1, %1};" : "=l"(r) : "f"(a)); return r;
}
__device__ __forceinline__ void fma2(ull& d, ull a, ull b) {
    asm("fma.rn.f32x2 %0, %1, %2, %3;" : "=l"(d) : "l"(a), "l"(b), "l"(d));
}
__device__ __forceinline__ float2 unpack2(ull v) {
    float2 f; asm("mov.b64 {%0, %1}, %2;" : "=f"(f.x), "=f"(f.y) : "l"(v)); return f;
}
__device__ __forceinline__ ull add2(ull a, ull b) {
    ull r; asm("add.rn.f32x2 %0, %1, %2;" : "=l"(r) : "l"(a), "l"(b)); return r;
}
__device__ __forceinline__ ull mul2(ull a, ull b) {
    ull r; asm("mul.rn.f32x2 %0, %1, %2;" : "=l"(r) : "l"(a), "l"(b)); return r;
}

union F4U { float4 f; ull u[2]; };

// ---------------------------------------------------------------------------
__global__ void qbias_kernel(const float* __restrict__ input1,
                             const float* __restrict__ Wq) {
    int b = blockIdx.x;
    int n = threadIdx.x;
    const float* x = input1 + b * Ee;
    float acc = 0.f;
#pragma unroll 4
    for (int e = 0; e < Ee; e++) acc += x[e] * Wq[e * HK + n];
    g_c1[b * HK + n] = acc;
}

// ---------------------------------------------------------------------------
// 64x256 GEMM, 256 threads, 8x8 micro-tile (rows tm*8.., cols tn*8..),
// double-buffered smem, packed f32x2. A [M,256] row-major, W [256,256].
// ---------------------------------------------------------------------------
#define G64_PROLOG()                                                      \
    __shared__ float As[2][8][68];                                        \
    __shared__ float Bs[2][8][264];                                       \
    const int tid = threadIdx.x;                                          \
    const int tm = tid >> 5, tn = tid & 31;                               \
    const int arow = tid >> 1, ac4 = (tid & 1) * 4;                       \
    const int bkr = tid >> 5, bn8 = (tid & 31) * 8;                       \
    ull acc2[8][4];                                                       \
    _Pragma("unroll") for (int i = 0; i < 8; i++)                         \
    _Pragma("unroll") for (int j = 0; j < 4; j++) acc2[i][j] = 0ull;

#define G64_STAGE(buf, av, bv0, bv1)                                      \
    if (tid < 128) {                                                      \
        As[buf][ac4 + 0][arow] = (av).x;                                  \
        As[buf][ac4 + 1][arow] = (av).y;                                  \
        As[buf][ac4 + 2][arow] = (av).z;                                  \
        As[buf][ac4 + 3][arow] = (av).w;                                  \
    }                                                                     \
    *(float4*)&Bs[buf][bkr][bn8] = (bv0);                                 \
    *(float4*)&Bs[buf][bkr][bn8 + 4] = (bv1);

#define G64_INNER(buf)                                                    \
    _Pragma("unroll")                                                     \
    for (int kk = 0; kk < 8; kk++) {                                      \
        float4 a0 = *(const float4*)&As[buf][kk][tm * 8];                 \
        float4 a1 = *(const float4*)&As[buf][kk][tm * 8 + 4];             \
        const ull* bp = (const ull*)&Bs[buf][kk][tn * 8];                 \
        ull b0 = bp[0], b1 = bp[1], b2 = bp[2], b3 = bp[3];               \
        float aa[8] = {a0.x, a0.y, a0.z, a0.w, a1.x, a1.y, a1.z, a1.w};   \
        _Pragma("unroll") for (int i = 0; i < 8; i++) {                   \
            ull ad = dup2(aa[i]);                                         \
            fma2(acc2[i][0], ad, b0);                                     \
            fma2(acc2[i][1], ad, b1);                                     \
            fma2(acc2[i][2], ad, b2);                                     \
            fma2(acc2[i][3], ad, b3);                                     \
        }                                                                 \
    }

#define G64_LOOP_NN(Aptr, Wptr, m0)                                       \
    {                                                                     \
        const float* Ag = (Aptr) + (size_t)((m0) + arow) * 256 + ac4;     \
        const float* Bg = (Wptr) + (size_t)bkr * 256 + bn8;               \
        float4 av = make_float4(0.f, 0.f, 0.f, 0.f);                      \
        if (tid < 128) av = *(const float4*)Ag;                           \
        float4 bv0 = *(const float4*)Bg;                                  \
        float4 bv1 = *(const float4*)(Bg + 4);                            \
        G64_STAGE(0, av, bv0, bv1);                                       \
        __syncthreads();                                                  \
        for (int k0 = 0; k0 < 256; k0 += 8) {                             \
            int buf = (k0 >> 3) & 1;                                      \
            if (k0 < 248) {                                               \
                if (tid < 128) av = *(const float4*)(Ag + k0 + 8);        \
                bv0 = *(const float4*)(Bg + (size_t)(k0 + 8) * 256);      \
                bv1 = *(const float4*)(Bg + (size_t)(k0 + 8) * 256 + 4);  \
            }                                                             \
            G64_INNER(buf);                                               \
            if (k0 < 248) {                                               \
                G64_STAGE(buf ^ 1, av, bv0, bv1);                         \
                __syncthreads();                                          \
            }                                                             \
        }                                                                 \
    }

// ---------------------------------------------------------------------------
// Fused projections: z=0 K, z=1 V, z=2 Q (+c1 + t*wq_last). Heads layout out.
// ---------------------------------------------------------------------------
__global__ __launch_bounds__(256, 2)
void proj_kernel(const float* __restrict__ enc, const float* __restrict__ inp2,
                 const float* __restrict__ Wk, const float* __restrict__ Wv,
                 const float* __restrict__ Wqm, const float* __restrict__ tvec,
                 const float* __restrict__ wql) {
    const int z = blockIdx.y;
    const float* A = (z == 2) ? inp2 : enc;
    const float* W = (z == 0) ? Wk : (z == 1) ? Wv : Wqm;
    float* C = (z == 0) ? g_Kt : (z == 1) ? g_Vt : g_Qt;
    const int m0 = blockIdx.x * 64;

    G64_PROLOG();
    G64_LOOP_NN(A, W, m0);

#pragma unroll
    for (int i = 0; i < 8; i++) {
        int m = m0 + tm * 8 + i;
        int bb = m >> 9, r = m & 511;
        int nb = tn * 8;
        float v[8];
#pragma unroll
        for (int j = 0; j < 4; j++) {
            float2 f = unpack2(acc2[i][j]);
            v[2 * j] = f.x; v[2 * j + 1] = f.y;
        }
        if (z == 2) {
            float t = tvec[m];
#pragma unroll
            for (int j = 0; j < 8; j++) {
                int n = nb + j;
                v[j] += g_c1[bb * HK + n] + t * wql[n];
            }
        }
        int h = nb >> 4, kcb = nb & 15;
        float* dst = C + (((size_t)(bb * Hh + h) * 512 + r) << 4) + kcb;
        *(float4*)dst = make_float4(v[0], v[1], v[2], v[3]);
        *(float4*)(dst + 4) = make_float4(v[4], v[5], v[6], v[7]);
    }
}

// ---------------------------------------------------------------------------
__global__ __launch_bounds__(256, 2)
void wc_kernel(const float* __restrict__ Wcw, const float* __restrict__ bias) {
    const int m0 = blockIdx.x * 64;
    G64_PROLOG();
    G64_LOOP_NN(g_attn, Wcw, m0);

#pragma unroll
    for (int i = 0; i < 8; i++) {
        int m = m0 + tm * 8 + i;
        int nb = tn * 8;
        float v[8];
#pragma unroll
        for (int j = 0; j < 4; j++) {
            float2 f = unpack2(acc2[i][j]);
            v[2 * j] = f.x + bias[nb + 2 * j];
            v[2 * j + 1] = f.y + bias[nb + 2 * j + 1];
        }
        float* dst = g_mh + (size_t)m * 256 + nb;
        *(float4*)dst = make_float4(v[0], v[1], v[2], v[3]);
        *(float4*)(dst + 4) = make_float4(v[4], v[5], v[6], v[7]);
    }
}

// ---------------------------------------------------------------------------
__device__ __forceinline__ float fast_tanh10(float x) {
    x = fminf(fmaxf(x, -15.f), 15.f);
    float e = __expf(2.f * x);
    return 10.f * (1.f - __fdividef(2.f, e + 1.f));
}

// ---------------------------------------------------------------------------
// Fused pointer scores + tanh clip + mask + FINAL SOFTMAX.
// Tile = 64 g x 512 p (full row in block), 256 threads.
// Thread (tm,tn): rows tm*8..+7, cols tn*16..+15. Row = one warp -> shfl softmax.
// ---------------------------------------------------------------------------
__global__ __launch_bounds__(256, 1)
void pointer_softmax(const float* __restrict__ enc, const float* __restrict__ mask,
                     float* __restrict__ out) {
    __shared__ float As[2][8][68];
    __shared__ float Bs[2][8][520];
    const int tid = threadIdx.x;
    const int b = blockIdx.y;
    const int g0 = blockIdx.x * 64;
    const int tm = tid >> 5, tn = tid & 31;
    const int arow = tid >> 1, ac4 = (tid & 1) * 4;
    const int pr = tid * 2;   // stages p rows pr, pr+1

    const float* A = g_mh + (size_t)b * Gg * HK;
    const float* Bm = enc + (size_t)b * Pp * Ee;

    ull acc2[8][8];
#pragma unroll
    for (int i = 0; i < 8; i++)
#pragma unroll
        for (int j = 0; j < 8; j++) acc2[i][j] = 0ull;

    const float* Ag = A + (size_t)(g0 + arow) * 256 + ac4;
    const float* Bg0 = Bm + (size_t)pr * 256;
    const float* Bg1 = Bm + (size_t)(pr + 1) * 256;

    float4 av = make_float4(0.f, 0.f, 0.f, 0.f);
    if (tid < 128) av = *(const float4*)Ag;
    float4 ba0 = *(const float4*)Bg0;
    float4 ba1 = *(const float4*)(Bg0 + 4);
    float4 bb0 = *(const float4*)Bg1;
    float4 bb1 = *(const float4*)(Bg1 + 4);

    // stage buf 0
    {
        if (tid < 128) {
            As[0][ac4 + 0][arow] = av.x; As[0][ac4 + 1][arow] = av.y;
            As[0][ac4 + 2][arow] = av.z; As[0][ac4 + 3][arow] = av.w;
        }
        Bs[0][0][pr] = ba0.x; Bs[0][1][pr] = ba0.y;
        Bs[0][2][pr] = ba0.z; Bs[0][3][pr] = ba0.w;
        Bs[0][4][pr] = ba1.x; Bs[0][5][pr] = ba1.y;
        Bs[0][6][pr] = ba1.z; Bs[0][7][pr] = ba1.w;
        Bs[0][0][pr + 1] = bb0.x; Bs[0][1][pr + 1] = bb0.y;
        Bs[0][2][pr + 1] = bb0.z; Bs[0][3][pr + 1] = bb0.w;
        Bs[0][4][pr + 1] = bb1.x; Bs[0][5][pr + 1] = bb1.y;
        Bs[0][6][pr + 1] = bb1.z; Bs[0][7][pr + 1] = bb1.w;
    }
    __syncthreads();

    for (int k0 = 0; k0 < 256; k0 += 8) {
        int buf = (k0 >> 3) & 1;
        if (k0 < 248) {
            if (tid < 128) av = *(const float4*)(Ag + k0 + 8);
            ba0 = *(const float4*)(Bg0 + k0 + 8);
            ba1 = *(const float4*)(Bg0 + k0 + 12);
            bb0 = *(const float4*)(Bg1 + k0 + 8);
            bb1 = *(const float4*)(Bg1 + k0 + 12);
        }
#pragma unroll
        for (int kk = 0; kk < 8; kk++) {
            float4 a0 = *(const float4*)&As[buf][kk][tm * 8];
            float4 a1 = *(const float4*)&As[buf][kk][tm * 8 + 4];
            const ull* bp = (const ull*)&Bs[buf][kk][tn * 16];
            ull b0 = bp[0], b1 = bp[1], b2 = bp[2], b3 = bp[3];
            ull b4 = bp[4], b5 = bp[5], b6 = bp[6], b7 = bp[7];
            float aa[8] = {a0.x, a0.y, a0.z, a0.w, a1.x, a1.y, a1.z, a1.w};
#pragma unroll
            for (int i = 0; i < 8; i++) {
                ull ad = dup2(aa[i]);
                fma2(acc2[i][0], ad, b0); fma2(acc2[i][1], ad, b1);
                fma2(acc2[i][2], ad, b2); fma2(acc2[i][3], ad, b3);
                fma2(acc2[i][4], ad, b4); fma2(acc2[i][5], ad, b5);
                fma2(acc2[i][6], ad, b6); fma2(acc2[i][7], ad, b7);
            }
        }
        if (k0 < 248) {
            int nb = buf ^ 1;
            if (tid < 128) {
                As[nb][ac4 + 0][arow] = av.x; As[nb][ac4 + 1][arow] = av.y;
                As[nb][ac4 + 2][arow] = av.z; As[nb][ac4 + 3][arow] = av.w;
            }
            Bs[nb][0][pr] = ba0.x; Bs[nb][1][pr] = ba0.y;
            Bs[nb][2][pr] = ba0.z; Bs[nb][3][pr] = ba0.w;
            Bs[nb][4][pr] = ba1.x; Bs[nb][5][pr] = ba1.y;
            Bs[nb][6][pr] = ba1.z; Bs[nb][7][pr] = ba1.w;
            Bs[nb][0][pr + 1] = bb0.x; Bs[nb][1][pr + 1] = bb0.y;
            Bs[nb][2][pr + 1] = bb0.z; Bs[nb][3][pr + 1] = bb0.w;
            Bs[nb][4][pr + 1] = bb1.x; Bs[nb][5][pr + 1] = bb1.y;
            Bs[nb][6][pr + 1] = bb1.z; Bs[nb][7][pr + 1] = bb1.w;
            __syncthreads();
        }
    }

    // epilogue: tanh clip + mask + row softmax (row owned by one warp)
#pragma unroll
    for (int i = 0; i < 8; i++) {
        int g = g0 + tm * 8 + i;
        size_t base = (size_t)(b * Gg + g) * Pp + tn * 16;
        float v[16];
#pragma unroll
        for (int j = 0; j < 8; j++) {
            float2 f = unpack2(acc2[i][j]);
            v[2 * j] = f.x; v[2 * j + 1] = f.y;
        }
#pragma unroll
        for (int j = 0; j < 4; j++) {
            float4 mk = *(const float4*)&mask[base + j * 4];
            v[4 * j + 0] = fast_tanh10(v[4 * j + 0] * 0.0625f) + mk.x;
            v[4 * j + 1] = fast_tanh10(v[4 * j + 1] * 0.0625f) + mk.y;
            v[4 * j + 2] = fast_tanh10(v[4 * j + 2] * 0.0625f) + mk.z;
            v[4 * j + 3] = fast_tanh10(v[4 * j + 3] * 0.0625f) + mk.w;
        }
        float mx = v[0];
#pragma unroll
        for (int j = 1; j < 16; j++) mx = fmaxf(mx, v[j]);
#pragma unroll
        for (int o = 16; o > 0; o >>= 1)
            mx = fmaxf(mx, __shfl_xor_sync(0xffffffffu, mx, o));
        float sum = 0.f;
#pragma unroll
        for (int j = 0; j < 16; j++) {
            v[j] = __expf(v[j] - mx);
            sum += v[j];
        }
#pragma unroll
        for (int o = 16; o > 0; o >>= 1)
            sum += __shfl_xor_sync(0xffffffffu, sum, o);
        float inv = __fdividef(1.f, sum);
#pragma unroll
        for (int j = 0; j < 4; j++) {
            *(float4*)&out[base + j * 4] =
                make_float4(v[4 * j] * inv, v[4 * j + 1] * inv,
                            v[4 * j + 2] * inv, v[4 * j + 3] * inv);
        }
    }
}

// ---------------------------------------------------------------------------
// Warp-autonomous attention, 4 queries per pass (R6 proven version).
// ---------------------------------------------------------------------------
#define AT_STR 20
#define ATTN_SMEM_BYTES (2 * 512 * AT_STR * 4)   // 81920 B

__global__ __launch_bounds__(256, 1)
void attn_kernel(const float* __restrict__ mask) {
    extern __shared__ float sm[];
    float* sK = sm;
    float* sV = sm + 512 * AT_STR;

    const int tid = threadIdx.x;
    const int gbase = blockIdx.x * 256;
    const int h = blockIdx.y, b = blockIdx.z;
    const float* Kb = g_Kt + (size_t)(b * Hh + h) * Pp * Kd;
    const float* Vb = g_Vt + (size_t)(b * Hh + h) * Pp * Kd;
    const float* Qb = g_Qt + (size_t)(b * Hh + h) * Gg * Kd;

    for (int i = tid; i < 2048; i += 256) {
        int p = i >> 2, c = (i & 3) * 4;
        *(float4*)&sK[p * AT_STR + c] = ((const float4*)Kb)[i];
        *(float4*)&sV[p * AT_STR + c] = ((const float4*)Vb)[i];
    }
    __syncthreads();

    const int warp = tid >> 5, lane = tid & 31;
    const int kcout = (((lane >> 4) & 1) << 3) | (((lane >> 3) & 1) << 2) |
                      (((lane >> 2) & 1) << 1) | ((lane >> 1) & 1);

    for (int pass = 0; pass < 8; pass++) {
        const int g0 = gbase + warp * 32 + pass * 4;

        F4U q[4][4];
#pragma unroll
        for (int qq = 0; qq < 4; qq++) {
            const float4* Qp = (const float4*)(Qb + (size_t)(g0 + qq) * 16);
            q[qq][0].f = Qp[0]; q[qq][1].f = Qp[1];
            q[qq][2].f = Qp[2]; q[qq][3].f = Qp[3];
        }

        float s[4][16];
#pragma unroll
        for (int i = 0; i < 16; i++) {
            const float* kr = &sK[(lane + 32 * i) * AT_STR];
            F4U k0, k1, k2, k3;
            k0.f = *(const float4*)kr;
            k1.f = *(const float4*)(kr + 4);
            k2.f = *(const float4*)(kr + 8);
            k3.f = *(const float4*)(kr + 12);
#pragma unroll
            for (int qq = 0; qq < 4; qq++) {
                ull a = 0ull;
                fma2(a, q[qq][0].u[0], k0.u[0]); fma2(a, q[qq][0].u[1], k0.u[1]);
                fma2(a, q[qq][1].u[0], k1.u[0]); fma2(a, q[qq][1].u[1], k1.u[1]);
                fma2(a, q[qq][2].u[0], k2.u[0]); fma2(a, q[qq][2].u[1], k2.u[1]);
                fma2(a, q[qq][3].u[0], k3.u[0]); fma2(a, q[qq][3].u[1], k3.u[1]);
                float2 f = unpack2(a);
                s[qq][i] = f.x + f.y;
            }
        }

        float inv[4];
#pragma unroll
        for (int qq = 0; qq < 4; qq++) {
            const float* mrow = mask + (size_t)(b * Gg + g0 + qq) * Pp + lane;
            float mk[16];
#pragma unroll
            for (int i = 0; i < 16; i++) mk[i] = mrow[32 * i];
#pragma unroll
            for (int i = 0; i < 16; i++) s[qq][i] = s[qq][i] * 0.25f + mk[i];

            float mx = s[qq][0];
#pragma unroll
            for (int i = 1; i < 16; i++) mx = fmaxf(mx, s[qq][i]);
#pragma unroll
            for (int o = 16; o > 0; o >>= 1)
                mx = fmaxf(mx, __shfl_xor_sync(0xffffffffu, mx, o));
            float sum = 0.f;
#pragma unroll
            for (int i = 0; i < 16; i++) {
                s[qq][i] = __expf(s[qq][i] - mx);
                sum += s[qq][i];
            }
#pragma unroll
            for (int o = 16; o > 0; o >>= 1)
                sum += __shfl_xor_sync(0xffffffffu, sum, o);
            inv[qq] = __fdividef(1.f, sum);
        }

        ull acc[4][8];
#pragma unroll
        for (int qq = 0; qq < 4; qq++)
#pragma unroll
            for (int j = 0; j < 8; j++) acc[qq][j] = 0ull;

#pragma unroll
        for (int i = 0; i < 16; i++) {
            const float* vr = &sV[(lane + 32 * i) * AT_STR];
            F4U v0, v1, v2, v3;
            v0.f = *(const float4*)vr;
            v1.f = *(const float4*)(vr + 4);
            v2.f = *(const float4*)(vr + 8);
            v3.f = *(const float4*)(vr + 12);
#pragma unroll
            for (int qq = 0; qq < 4; qq++) {
                ull wd = dup2(s[qq][i]);
                fma2(acc[qq][0], wd, v0.u[0]); fma2(acc[qq][1], wd, v0.u[1]);
                fma2(acc[qq][2], wd, v1.u[0]); fma2(acc[qq][3], wd, v1.u[1]);
                fma2(acc[qq][4], wd, v2.u[0]); fma2(acc[qq][5], wd, v2.u[1]);
                fma2(acc[qq][6], wd, v3.u[0]); fma2(acc[qq][7], wd, v3.u[1]);
            }
        }

#pragma unroll
        for (int qq = 0; qq < 4; qq++) {
            const ull ivd = dup2(inv[qq]);
            ull a8[8];
#pragma unroll
            for (int j = 0; j < 8; j++) a8[j] = mul2(acc[qq][j], ivd);

            ull n4[4];
#pragma unroll
            for (int j = 0; j < 4; j++) {
                ull snd = (lane & 16) ? a8[j] : a8[j + 4];
                ull kp  = (lane & 16) ? a8[j + 4] : a8[j];
                n4[j] = add2(kp, __shfl_xor_sync(0xffffffffu, snd, 16));
            }
            ull n2[2];
#pragma unroll
            for (int j = 0; j < 2; j++) {
                ull snd = (lane & 8) ? n4[j] : n4[j + 2];
                ull kp  = (lane & 8) ? n4[j + 2] : n4[j];
                n2[j] = add2(kp, __shfl_xor_sync(0xffffffffu, snd, 8));
            }
            ull n1;
            {
                ull snd = (lane & 4) ? n2[0] : n2[1];
                ull kp  = (lane & 4) ? n2[1] : n2[0];
                n1 = add2(kp, __shfl_xor_sync(0xffffffffu, snd, 4));
            }
            float2 t = unpack2(n1);
            float fs = (lane & 2) ? t.x : t.y;
            float fk = (lane & 2) ? t.y : t.x;
            float f = fk + __shfl_xor_sync(0xffffffffu, fs, 2);
            f += __shfl_xor_sync(0xffffffffu, f, 1);

            if (!(lane & 1))
                g_attn[(size_t)(b * Gg + g0 + qq) * HK + h * 16 + kcout] = f;
        }
    }
}

// ---------------------------------------------------------------------------
extern "C" void kernel_launch(void* const* d_in, const int* in_sizes, int n_in,
                              void* d_out, int out_size) {
    const float* input1 = (const float*)d_in[0];
    const float* input2 = (const float*)d_in[1];
    const float* ctime  = (const float*)d_in[2];
    const float* mask   = (const float*)d_in[3];
    const float* enc    = (const float*)d_in[4];
    const float* Wq     = (const float*)d_in[5];
    const float* Wk     = (const float*)d_in[6];
    const float* Wv     = (const float*)d_in[7];
    const float* Wcw    = (const float*)d_in[8];
    const float* Wcb    = (const float*)d_in[9];
    float* out = (float*)d_out;

    qbias_kernel<<<Bb, 256>>>(input1, Wq);

    proj_kernel<<<dim3(128, 3), 256>>>(enc, input2, Wk, Wv,
                                       Wq + Ee * HK, ctime, Wq + 2 * Ee * HK);

    cudaFuncSetAttribute(attn_kernel, cudaFuncAttributeMaxDynamicSharedMemorySize,
                         ATTN_SMEM_BYTES);
    attn_kernel<<<dim3(2, Hh, Bb), 256, ATTN_SMEM_BYTES>>>(mask);

    wc_kernel<<<128, 256>>>(Wcw, Wcb);

    pointer_softmax<<<dim3(8, Bb), 256>>>(enc, mask, out);
}

// round 8
// speedup vs baseline: 1.2495x; 1.2495x over previous
#include <cuda_runtime.h>
#include <math.h>

#define Bb 16
#define Gg 512
#define Pp 512
#define Ee 256
#define Hh 16
#define Kd 16
#define HK 256

typedef unsigned long long ull;

// Scratch (device globals: allocation-free rule)
__device__ float g_c1[Bb * HK];
__device__ float g_Kt[Bb * Hh * Pp * Kd];   // [B,H,P,Kd]
__device__ float g_Vt[Bb * Hh * Pp * Kd];
__device__ float g_Qt[Bb * Hh * Gg * Kd];
__device__ float g_attn[Bb * Gg * HK];
__device__ float g_mh[Bb * Gg * HK];
__device__ float g_s2[Bb * Gg * Pp];

// ---- packed f32x2 helpers ---------------------------------------------------
__device__ __forceinline__ ull dup2(float a) {
    ull r; asm("mov.b64 %0, {%1, %1};" : "=l"(r) : "f"(a)); return r;
}
__device__ __forceinline__ void fma2(ull& d, ull a, ull b) {
    asm("fma.rn.f32x2 %0, %1, %2, %3;" : "=l"(d) : "l"(a), "l"(b), "l"(d));
}
__device__ __forceinline__ float2 unpack2(ull v) {
    float2 f; asm("mov.b64 {%0, %1}, %2;" : "=f"(f.x), "=f"(f.y) : "l"(v)); return f;
}
__device__ __forceinline__ ull add2(ull a, ull b) {
    ull r; asm("add.rn.f32x2 %0, %1, %2;" : "=l"(r) : "l"(a), "l"(b)); return r;
}
__device__ __forceinline__ ull mul2(ull a, ull b) {
    ull r; asm("mul.rn.f32x2 %0, %1, %2;" : "=l"(r) : "l"(a), "l"(b)); return r;
}
__device__ __forceinline__ float ex2(float x) {
    float r; asm("ex2.approx.f32 %0, %1;" : "=f"(r) : "f"(x)); return r;
}

#define L2E 1.44269504089f

union F4U { float4 f; ull u[2]; };

// ---------------------------------------------------------------------------
__global__ void qbias_kernel(const float* __restrict__ input1,
                             const float* __restrict__ Wq) {
    int b = blockIdx.x;
    int n = threadIdx.x;
    const float* x = input1 + b * Ee;
    float acc = 0.f;
#pragma unroll 4
    for (int e = 0; e < Ee; e++) acc += x[e] * Wq[e * HK + n];
    g_c1[b * HK + n] = acc;
}

// ---------------------------------------------------------------------------
// 128x128 tile GEMM (256 threads, 8x8 micro-tile via 8x4 packed f32x2, BK=8)
// ---------------------------------------------------------------------------
#define GEMM_PROLOG()                                                     \
    __shared__ float As[8][132];                                          \
    __shared__ float Bs[8][132];                                          \
    const int tid = threadIdx.x;                                          \
    const int warp = tid >> 5, lane = tid & 31;                           \
    const int tm = ((warp >> 2) << 3) + (lane >> 2);                      \
    const int tn = ((warp & 3) << 2) + (lane & 3);                        \
    const int ar = tid >> 1, ac = (tid & 1) * 4;                          \
    const int br = tid >> 5, bc = (tid & 31) * 4;                         \
    ull acc2[8][4];                                                       \
    _Pragma("unroll") for (int i = 0; i < 8; i++)                         \
    _Pragma("unroll") for (int j = 0; j < 4; j++) acc2[i][j] = 0ull;

#define GEMM_INNER2()                                                     \
    _Pragma("unroll")                                                     \
    for (int kk = 0; kk < 8; kk++) {                                      \
        float4 a0 = *(const float4*)&As[kk][tm * 8];                      \
        float4 a1 = *(const float4*)&As[kk][tm * 8 + 4];                  \
        const ull* bp = (const ull*)&Bs[kk][tn * 8];                      \
        ull b0 = bp[0], b1 = bp[1], b2 = bp[2], b3 = bp[3];               \
        float aa[8] = {a0.x, a0.y, a0.z, a0.w, a1.x, a1.y, a1.z, a1.w};   \
        _Pragma("unroll") for (int i = 0; i < 8; i++) {                   \
            ull ad = dup2(aa[i]);                                         \
            fma2(acc2[i][0], ad, b0);                                     \
            fma2(acc2[i][1], ad, b1);                                     \
            fma2(acc2[i][2], ad, b2);                                     \
            fma2(acc2[i][3], ad, b3);                                     \
        }                                                                 \
    }

#define GEMM_LOOP_NN(Aptr, Wptr, m0, n0)                                  \
    {                                                                     \
        const float* Ag = (Aptr) + (size_t)((m0) + ar) * 256 + ac;        \
        const float* Bg = (Wptr) + (size_t)br * 256 + (n0) + bc;          \
        float4 av = *(const float4*)Ag;                                   \
        float4 bv = *(const float4*)Bg;                                   \
        for (int k0 = 0; k0 < 256; k0 += 8) {                             \
            As[ac + 0][ar] = av.x; As[ac + 1][ar] = av.y;                 \
            As[ac + 2][ar] = av.z; As[ac + 3][ar] = av.w;                 \
            *(float4*)&Bs[br][bc] = bv;                                   \
            __syncthreads();                                              \
            if (k0 < 248) {                                               \
                av = *(const float4*)(Ag + k0 + 8);                       \
                bv = *(const float4*)(Bg + (size_t)(k0 + 8) * 256);       \
            }                                                             \
            GEMM_INNER2();                                                \
            __syncthreads();                                              \
        }                                                                 \
    }

#define GEMM_LOOP_NT(Aptr, Bptr, m0, n0)                                  \
    {                                                                     \
        const float* Ag = (Aptr) + (size_t)((m0) + ar) * 256 + ac;        \
        const float* Bg2 = (Bptr) + (size_t)((n0) + ar) * 256 + ac;       \
        float4 av = *(const float4*)Ag;                                   \
        float4 bv = *(const float4*)Bg2;                                  \
        for (int k0 = 0; k0 < 256; k0 += 8) {                             \
            As[ac + 0][ar] = av.x; As[ac + 1][ar] = av.y;                 \
            As[ac + 2][ar] = av.z; As[ac + 3][ar] = av.w;                 \
            Bs[ac + 0][ar] = bv.x; Bs[ac + 1][ar] = bv.y;                 \
            Bs[ac + 2][ar] = bv.z; Bs[ac + 3][ar] = bv.w;                 \
            __syncthreads();                                              \
            if (k0 < 248) {                                               \
                av = *(const float4*)(Ag + k0 + 8);                       \
                bv = *(const float4*)(Bg2 + k0 + 8);                      \
            }                                                             \
            GEMM_INNER2();                                                \
            __syncthreads();                                              \
        }                                                                 \
    }

// ---------------------------------------------------------------------------
// Fused projections: z=0 K, z=1 V, z=2 Q (+c1 + t*wq_last). Heads layout out.
// ---------------------------------------------------------------------------
__global__ __launch_bounds__(256, 2)
void proj_kernel(const float* __restrict__ enc, const float* __restrict__ inp2,
                 const float* __restrict__ Wk, const float* __restrict__ Wv,
                 const float* __restrict__ Wqm, const float* __restrict__ tvec,
                 const float* __restrict__ wql) {
    const int z = blockIdx.z;
    const float* A = (z == 2) ? inp2 : enc;
    const float* W = (z == 0) ? Wk : (z == 1) ? Wv : Wqm;
    float* C = (z == 0) ? g_Kt : (z == 1) ? g_Vt : g_Qt;
    const int m0 = blockIdx.x * 128, n0 = blockIdx.y * 128;

    GEMM_PROLOG();
    GEMM_LOOP_NN(A, W, m0, n0);

#pragma unroll
    for (int i = 0; i < 8; i++) {
        int m = m0 + tm * 8 + i;
        int bb = m >> 9, r = m & 511;
        int nb = n0 + tn * 8;
        float v[8];
#pragma unroll
        for (int j = 0; j < 4; j++) {
            float2 f = unpack2(acc2[i][j]);
            v[2 * j] = f.x; v[2 * j + 1] = f.y;
        }
        if (z == 2) {
            float t = tvec[m];
#pragma unroll
            for (int j = 0; j < 8; j++) {
                int n = nb + j;
                v[j] += g_c1[bb * HK + n] + t * wql[n];
            }
        }
        int h = nb >> 4, kcb = nb & 15;
        float* dst = C + (((size_t)(bb * Hh + h) * 512 + r) << 4) + kcb;
        *(float4*)dst = make_float4(v[0], v[1], v[2], v[3]);
        *(float4*)(dst + 4) = make_float4(v[4], v[5], v[6], v[7]);
    }
}

// ---------------------------------------------------------------------------
__global__ __launch_bounds__(256, 2)
void wc_kernel(const float* __restrict__ Wcw, const float* __restrict__ bias) {
    const int m0 = blockIdx.x * 128, n0 = blockIdx.y * 128;
    GEMM_PROLOG();
    GEMM_LOOP_NN(g_attn, Wcw, m0, n0);

#pragma unroll
    for (int i = 0; i < 8; i++) {
        int m = m0 + tm * 8 + i;
        int nb = n0 + tn * 8;
        float v[8];
#pragma unroll
        for (int j = 0; j < 4; j++) {
            float2 f = unpack2(acc2[i][j]);
            v[2 * j] = f.x + bias[nb + 2 * j];
            v[2 * j + 1] = f.y + bias[nb + 2 * j + 1];
        }
        float* dst = g_mh + (size_t)m * 256 + nb;
        *(float4*)dst = make_float4(v[0], v[1], v[2], v[3]);
        *(float4*)(dst + 4) = make_float4(v[4], v[5], v[6], v[7]);
    }
}

// ---------------------------------------------------------------------------
__device__ __forceinline__ float fast_tanh10(float x) {
    x = fminf(fmaxf(x, -15.f), 15.f);
    float e = __expf(2.f * x);
    return 10.f * (1.f - __fdividef(2.f, e + 1.f));
}

__global__ __launch_bounds__(256, 2)
void pointer_gemm(const float* __restrict__ enc, const float* __restrict__ mask) {
    const int b = blockIdx.z;
    const int g0 = blockIdx.x * 128, p0 = blockIdx.y * 128;
    const float* A = g_mh + (size_t)b * Gg * HK;
    const float* Bm = enc + (size_t)b * Pp * Ee;

    GEMM_PROLOG();
    GEMM_LOOP_NT(A, Bm, g0, p0);

#pragma unroll
    for (int i = 0; i < 8; i++) {
        int g = g0 + tm * 8 + i;
        size_t base = (size_t)(b * Gg + g) * Pp + p0 + tn * 8;
        float v[8];
#pragma unroll
        for (int j = 0; j < 4; j++) {
            float2 f = unpack2(acc2[i][j]);
            v[2 * j] = fast_tanh10(f.x * 0.0625f) + mask[base + 2 * j];
            v[2 * j + 1] = fast_tanh10(f.y * 0.0625f) + mask[base + 2 * j + 1];
        }
        *(float4*)&g_s2[base] = make_float4(v[0], v[1], v[2], v[3]);
        *(float4*)&g_s2[base + 4] = make_float4(v[4], v[5], v[6], v[7]);
    }
}

// ---------------------------------------------------------------------------
// Warp-autonomous attention, 4 queries per pass. R6-proven structure.
// R8 tweaks: mask prefetch before score phase (pre-scaled by log2e); exp via
// raw ex2 with scale folded into one FMA.
// ---------------------------------------------------------------------------
#define AT_STR 20
#define ATTN_SMEM_BYTES (2 * 512 * AT_STR * 4)   // 81920 B

__global__ __launch_bounds__(256, 1)
void attn_kernel(const float* __restrict__ mask) {
    extern __shared__ float sm[];
    float* sK = sm;
    float* sV = sm + 512 * AT_STR;

    const int tid = threadIdx.x;
    const int gbase = blockIdx.x * 256;
    const int h = blockIdx.y, b = blockIdx.z;
    const float* Kb = g_Kt + (size_t)(b * Hh + h) * Pp * Kd;
    const float* Vb = g_Vt + (size_t)(b * Hh + h) * Pp * Kd;
    const float* Qb = g_Qt + (size_t)(b * Hh + h) * Gg * Kd;

    for (int i = tid; i < 2048; i += 256) {
        int p = i >> 2, c = (i & 3) * 4;
        *(float4*)&sK[p * AT_STR + c] = ((const float4*)Kb)[i];
        *(float4*)&sV[p * AT_STR + c] = ((const float4*)Vb)[i];
    }
    __syncthreads();   // the ONLY block barrier

    const int warp = tid >> 5, lane = tid & 31;
    const int kcout = (((lane >> 4) & 1) << 3) | (((lane >> 3) & 1) << 2) |
                      (((lane >> 2) & 1) << 1) | ((lane >> 1) & 1);
    const float SC2 = 0.25f * L2E;   // score scale folded with log2e

    for (int pass = 0; pass < 8; pass++) {
        const int g0 = gbase + warp * 32 + pass * 4;

        // 4 query vectors (uniform across warp)
        F4U q[4][4];
#pragma unroll
        for (int qq = 0; qq < 4; qq++) {
            const float4* Qp = (const float4*)(Qb + (size_t)(g0 + qq) * 16);
            q[qq][0].f = Qp[0]; q[qq][1].f = Qp[1];
            q[qq][2].f = Qp[2]; q[qq][3].f = Qp[3];
        }

        // PREFETCH masks for all 4 queries (hidden behind score fma2 stream),
        // pre-scaled by log2e.
        float mk[4][16];
#pragma unroll
        for (int qq = 0; qq < 4; qq++) {
            const float* mrow = mask + (size_t)(b * Gg + g0 + qq) * Pp + lane;
#pragma unroll
            for (int i = 0; i < 16; i++) mk[qq][i] = mrow[32 * i] * L2E;
        }

        // scores: each K row read once serves 4 queries
        float s[4][16];
#pragma unroll
        for (int i = 0; i < 16; i++) {
            const float* kr = &sK[(lane + 32 * i) * AT_STR];
            F4U k0, k1, k2, k3;
            k0.f = *(const float4*)kr;
            k1.f = *(const float4*)(kr + 4);
            k2.f = *(const float4*)(kr + 8);
            k3.f = *(const float4*)(kr + 12);
#pragma unroll
            for (int qq = 0; qq < 4; qq++) {
                ull a = 0ull;
                fma2(a, q[qq][0].u[0], k0.u[0]); fma2(a, q[qq][0].u[1], k0.u[1]);
                fma2(a, q[qq][1].u[0], k1.u[0]); fma2(a, q[qq][1].u[1], k1.u[1]);
                fma2(a, q[qq][2].u[0], k2.u[0]); fma2(a, q[qq][2].u[1], k2.u[1]);
                fma2(a, q[qq][3].u[0], k3.u[0]); fma2(a, q[qq][3].u[1], k3.u[1]);
                float2 f = unpack2(a);
                s[qq][i] = f.x + f.y;
            }
        }

        // softmax per query (log2 domain: s*SC2 + mk, ex2)
        float inv[4];
#pragma unroll
        for (int qq = 0; qq < 4; qq++) {
#pragma unroll
            for (int i = 0; i < 16; i++)
                s[qq][i] = fmaf(s[qq][i], SC2, mk[qq][i]);

            float mx = s[qq][0];
#pragma unroll
            for (int i = 1; i < 16; i++) mx = fmaxf(mx, s[qq][i]);
#pragma unroll
            for (int o = 16; o > 0; o >>= 1)
                mx = fmaxf(mx, __shfl_xor_sync(0xffffffffu, mx, o));
            float sum = 0.f;
#pragma unroll
            for (int i = 0; i < 16; i++) {
                s[qq][i] = ex2(s[qq][i] - mx);
                sum += s[qq][i];
            }
#pragma unroll
            for (int o = 16; o > 0; o >>= 1)
                sum += __shfl_xor_sync(0xffffffffu, sum, o);
            inv[qq] = __fdividef(1.f, sum);
        }

        // AV: each V row read once serves 4 queries
        ull acc[4][8];
#pragma unroll
        for (int qq = 0; qq < 4; qq++)
#pragma unroll
            for (int j = 0; j < 8; j++) acc[qq][j] = 0ull;

#pragma unroll
        for (int i = 0; i < 16; i++) {
            const float* vr = &sV[(lane + 32 * i) * AT_STR];
            F4U v0, v1, v2, v3;
            v0.f = *(const float4*)vr;
            v1.f = *(const float4*)(vr + 4);
            v2.f = *(const float4*)(vr + 8);
            v3.f = *(const float4*)(vr + 12);
#pragma unroll
            for (int qq = 0; qq < 4; qq++) {
                ull wd = dup2(s[qq][i]);
                fma2(acc[qq][0], wd, v0.u[0]); fma2(acc[qq][1], wd, v0.u[1]);
                fma2(acc[qq][2], wd, v1.u[0]); fma2(acc[qq][3], wd, v1.u[1]);
                fma2(acc[qq][4], wd, v2.u[0]); fma2(acc[qq][5], wd, v2.u[1]);
                fma2(acc[qq][6], wd, v3.u[0]); fma2(acc[qq][7], wd, v3.u[1]);
            }
        }

        // per-query: scale, butterfly reduce-scatter, write
#pragma unroll
        for (int qq = 0; qq < 4; qq++) {
            const ull ivd = dup2(inv[qq]);
            ull a8[8];
#pragma unroll
            for (int j = 0; j < 8; j++) a8[j] = mul2(acc[qq][j], ivd);

            ull n4[4];
#pragma unroll
            for (int j = 0; j < 4; j++) {
                ull snd = (lane & 16) ? a8[j] : a8[j + 4];
                ull kp  = (lane & 16) ? a8[j + 4] : a8[j];
                n4[j] = add2(kp, __shfl_xor_sync(0xffffffffu, snd, 16));
            }
            ull n2[2];
#pragma unroll
            for (int j = 0; j < 2; j++) {
                ull snd = (lane & 8) ? n4[j] : n4[j + 2];
                ull kp  = (lane & 8) ? n4[j + 2] : n4[j];
                n2[j] = add2(kp, __shfl_xor_sync(0xffffffffu, snd, 8));
            }
            ull n1;
            {
                ull snd = (lane & 4) ? n2[0] : n2[1];
                ull kp  = (lane & 4) ? n2[1] : n2[0];
                n1 = add2(kp, __shfl_xor_sync(0xffffffffu, snd, 4));
            }
            float2 t = unpack2(n1);
            float fs = (lane & 2) ? t.x : t.y;
            float fk = (lane & 2) ? t.y : t.x;
            float f = fk + __shfl_xor_sync(0xffffffffu, fs, 2);
            f += __shfl_xor_sync(0xffffffffu, f, 1);

            if (!(lane & 1))
                g_attn[(size_t)(b * Gg + g0 + qq) * HK + h * 16 + kcout] = f;
        }
    }
}

// ---------------------------------------------------------------------------
// Row softmax over P=512. Max-pass eliminated: scores are 10*tanh(..)+mask,
// bounded above by 10, so exp(v-10) cannot overflow.
// ---------------------------------------------------------------------------
__global__ __launch_bounds__(256)
void softmax_kernel(float* __restrict__ out) {
    __shared__ float sred[8];
    __shared__ float sinv;
    const int row = blockIdx.x;
    const int tid = threadIdx.x;
    const float* in = g_s2 + (size_t)row * Pp;

    float v0 = in[tid], v1 = in[tid + 256];
    float e0 = ex2(fmaf(v0, L2E, -10.f * L2E));
    float e1 = ex2(fmaf(v1, L2E, -10.f * L2E));
    float lsum = e0 + e1;
#pragma unroll
    for (int o = 16; o > 0; o >>= 1)
        lsum += __shfl_xor_sync(0xffffffffu, lsum, o);
    if ((tid & 31) == 0) sred[tid >> 5] = lsum;
    __syncthreads();
    if (tid == 0) {
        float s = 0.f;
#pragma unroll
        for (int w = 0; w < 8; w++) s += sred[w];
        sinv = 1.f / s;
    }
    __syncthreads();
    float inv = sinv;
    out[(size_t)row * Pp + tid] = e0 * inv;
    out[(size_t)row * Pp + tid + 256] = e1 * inv;
}

// ---------------------------------------------------------------------------
extern "C" void kernel_launch(void* const* d_in, const int* in_sizes, int n_in,
                              void* d_out, int out_size) {
    const float* input1 = (const float*)d_in[0];
    const float* input2 = (const float*)d_in[1];
    const float* ctime  = (const float*)d_in[2];
    const float* mask   = (const float*)d_in[3];
    const float* enc    = (const float*)d_in[4];
    const float* Wq     = (const float*)d_in[5];
    const float* Wk     = (const float*)d_in[6];
    const float* Wv     = (const float*)d_in[7];
    const float* Wcw    = (const float*)d_in[8];
    const float* Wcb    = (const float*)d_in[9];
    float* out = (float*)d_out;

    qbias_kernel<<<Bb, 256>>>(input1, Wq);

    proj_kernel<<<dim3(64, 2, 3), 256>>>(enc, input2, Wk, Wv,
                                         Wq + Ee * HK, ctime, Wq + 2 * Ee * HK);

    cudaFuncSetAttribute(attn_kernel, cudaFuncAttributeMaxDynamicSharedMemorySize,
                         ATTN_SMEM_BYTES);
    attn_kernel<<<dim3(2, Hh, Bb), 256, ATTN_SMEM_BYTES>>>(mask);

    wc_kernel<<<dim3(64, 2), 256>>>(Wcw, Wcb);

    pointer_gemm<<<dim3(4, 4, Bb), 256>>>(enc, mask);

    softmax_kernel<<<Bb * Gg, 256>>>(out);
}

// round 10
// speedup vs baseline: 1.4168x; 1.1339x over previous
#include <cuda_runtime.h>
#include <cuda_bf16.h>
#include <math.h>
#include <cstdint>

#define Bb 16
#define Gg 512
#define Pp 512
#define Ee 256
#define Hh 16
#define Kd 16
#define HK 256

typedef unsigned long long ull;

// ---------------- device globals (allocation-free rule) ----------------
__device__ float g_c1[Bb * HK];
__device__ float g_Kt[Bb * Hh * Pp * Kd];
__device__ float g_Vt[Bb * Hh * Pp * Kd];
__device__ float g_Qt[Bb * Hh * Gg * Kd];
__device__ float g_s2[Bb * Gg * Pp];

#define NBIG (Bb * Gg * HK)   // 2097152
__device__ __nv_bfloat16 e_h[NBIG],  e_l[NBIG];    // enc split
__device__ __nv_bfloat16 i2_h[NBIG], i2_l[NBIG];   // input2 split
__device__ __nv_bfloat16 at_h[NBIG], at_l[NBIG];   // attention out split
__device__ __nv_bfloat16 mh_h[NBIG], mh_l[NBIG];   // mh split
__device__ __nv_bfloat16 wkT_h[HK * HK], wkT_l[HK * HK];
__device__ __nv_bfloat16 wvT_h[HK * HK], wvT_l[HK * HK];
__device__ __nv_bfloat16 wqT_h[HK * HK], wqT_l[HK * HK];
__device__ __nv_bfloat16 wcT_h[HK * HK], wcT_l[HK * HK];

// ---------------- packed f32x2 helpers (attention) ----------------
__device__ __forceinline__ ull dup2(float a) {
    ull r; asm("mov.b64 %0, {%1, %1};" : "=l"(r) : "f"(a)); return r;
}
__device__ __forceinline__ void fma2(ull& d, ull a, ull b) {
    asm("fma.rn.f32x2 %0, %1, %2, %3;" : "=l"(d) : "l"(a), "l"(b), "l"(d));
}
__device__ __forceinline__ float2 unpack2(ull v) {
    float2 f; asm("mov.b64 {%0, %1}, %2;" : "=f"(f.x), "=f"(f.y) : "l"(v)); return f;
}
__device__ __forceinline__ ull add2(ull a, ull b) {
    ull r; asm("add.rn.f32x2 %0, %1, %2;" : "=l"(r) : "l"(a), "l"(b)); return r;
}
__device__ __forceinline__ ull mul2(ull a, ull b) {
    ull r; asm("mul.rn.f32x2 %0, %1, %2;" : "=l"(r) : "l"(a), "l"(b)); return r;
}
__device__ __forceinline__ float ex2f(float x) {
    float r; asm("ex2.approx.f32 %0, %1;" : "=f"(r) : "f"(x)); return r;
}
#define L2E 1.44269504089f
union F4U { float4 f; ull u[2]; };

// ---------------- mma.sync helpers (compute_103-safe HMMA path) ----------------
__device__ __forceinline__ uint32_t smem_u32(const void* p) {
    uint32_t a;
    asm("{ .reg .u64 t; cvta.to.shared.u64 t, %1; cvt.u32.u64 %0, t; }" : "=r"(a) : "l"(p));
    return a;
}
__device__ __forceinline__ void ldm_x4(uint32_t* r, uint32_t addr) {
    asm volatile("ldmatrix.sync.aligned.m8n8.x4.shared.b16 {%0,%1,%2,%3}, [%4];"
                 : "=r"(r[0]), "=r"(r[1]), "=r"(r[2]), "=r"(r[3]) : "r"(addr));
}
__device__ __forceinline__ void mma_bf16(float* d, const uint32_t* a, const uint32_t* b) {
    asm volatile("mma.sync.aligned.m16n8k16.row.col.f32.bf16.bf16.f32 "
                 "{%0,%1,%2,%3}, {%4,%5,%6,%7}, {%8,%9}, {%0,%1,%2,%3};"
                 : "+f"(d[0]), "+f"(d[1]), "+f"(d[2]), "+f"(d[3])
                 : "r"(a[0]), "r"(a[1]), "r"(a[2]), "r"(a[3]), "r"(b[0]), "r"(b[1]));
}

// SMEM: 4 tiles of 128 rows x 144B (64 bf16 used, pad to 72 -> conflict-free ldmatrix)
#define ROWB 144
#define T_AH 0u
#define T_AL 18432u
#define T_BH 36864u
#define T_BL 55296u
#define MMA_SMEM_BYTES 73728

// ---------------------------------------------------------------------------
// Core: acc[2][8][4] += (Ah+Al)[128x256] . (Bh+Bl)[128x256]^T  (both K-major)
// 256 threads, 8 warps as 4(M) x 2(N); warp tile 32x64; K staged in 4 chunks.
// ---------------------------------------------------------------------------
__device__ __forceinline__ void mma_gemm_tile(
    const __nv_bfloat16* __restrict__ Ah, const __nv_bfloat16* __restrict__ Al,
    const __nv_bfloat16* __restrict__ Bh, const __nv_bfloat16* __restrict__ Bl,
    char* smem, float acc[2][8][4])
{
    const int tid = threadIdx.x;
    const int warp = tid >> 5, lane = tid & 31;
    const int wm = (warp >> 1) * 32;
    const int wn = (warp & 1) * 64;
    const uint32_t sb = smem_u32(smem);

    const int a_r = lane & 15;
    const int a_kh = ((lane >> 4) & 1) << 3;
    const int b_r = (lane & 7) + (((lane >> 4) & 1) << 3);
    const int b_kh = ((lane >> 3) & 1) << 3;

    const __nv_bfloat16* srcs[4] = {Ah, Al, Bh, Bl};
    const uint32_t offs[4] = {T_AH, T_AL, T_BH, T_BL};

    for (int c = 0; c < 4; c++) {
        const int k0 = c * 64;
        // stage: 128 rows x 8 x 16B per tensor
#pragma unroll
        for (int a = 0; a < 4; a++) {
            const uint4* s = (const uint4*)(srcs[a] + k0);
#pragma unroll
            for (int i = 0; i < 4; i++) {
                int t = tid + (i << 8);
                int r = t >> 3, cc = t & 7;
                uint4 v = s[r * 32 + cc];
                *(uint4*)(smem + offs[a] + r * ROWB + cc * 16) = v;
            }
        }
        __syncthreads();

#pragma unroll
        for (int ks = 0; ks < 4; ks++) {
            const int kb = ks * 32;   // bytes (16 bf16 per kstep)

            uint32_t af[2][4];
#pragma unroll
            for (int mt = 0; mt < 2; mt++)
                ldm_x4(af[mt], sb + T_AH + (wm + mt * 16 + a_r) * ROWB + kb + a_kh * 2);

            uint32_t bh[4][4], bl[4][4];
#pragma unroll
            for (int ng = 0; ng < 4; ng++) {
                uint32_t ro = (wn + ng * 16 + b_r) * ROWB + kb + b_kh * 2;
                ldm_x4(bh[ng], sb + T_BH + ro);
                ldm_x4(bl[ng], sb + T_BL + ro);
            }

            // Ah*Bh + Ah*Bl
#pragma unroll
            for (int mt = 0; mt < 2; mt++)
#pragma unroll
                for (int ng = 0; ng < 4; ng++) {
                    mma_bf16(acc[mt][ng * 2],     af[mt], &bh[ng][0]);
                    mma_bf16(acc[mt][ng * 2 + 1], af[mt], &bh[ng][2]);
                    mma_bf16(acc[mt][ng * 2],     af[mt], &bl[ng][0]);
                    mma_bf16(acc[mt][ng * 2 + 1], af[mt], &bl[ng][2]);
                }

            // Al*Bh (reuse bh regs, reload A from lo tile)
#pragma unroll
            for (int mt = 0; mt < 2; mt++)
                ldm_x4(af[mt], sb + T_AL + (wm + mt * 16 + a_r) * ROWB + kb + a_kh * 2);
#pragma unroll
            for (int mt = 0; mt < 2; mt++)
#pragma unroll
                for (int ng = 0; ng < 4; ng++) {
                    mma_bf16(acc[mt][ng * 2],     af[mt], &bh[ng][0]);
                    mma_bf16(acc[mt][ng * 2 + 1], af[mt], &bh[ng][2]);
                }
        }
        __syncthreads();
    }
}

// ---------------------------------------------------------------------------
// conversion kernels
// ---------------------------------------------------------------------------
__global__ void split_kernel(const float* __restrict__ src,
                             __nv_bfloat16* __restrict__ h,
                             __nv_bfloat16* __restrict__ l, int n) {
    int i = blockIdx.x * 256 + threadIdx.x;
    if (i < n) {
        float x = src[i];
        __nv_bfloat16 hb = __float2bfloat16(x);
        h[i] = hb;
        l[i] = __float2bfloat16(x - __bfloat162float(hb));
    }
}

__global__ void wsplit_kernel(const float* __restrict__ W,
                              __nv_bfloat16* __restrict__ th,
                              __nv_bfloat16* __restrict__ tl) {
    int k = blockIdx.x, n = threadIdx.x;
    float x = W[k * 256 + n];
    __nv_bfloat16 hb = __float2bfloat16(x);
    th[n * 256 + k] = hb;
    tl[n * 256 + k] = __float2bfloat16(x - __bfloat162float(hb));
}

// ---------------------------------------------------------------------------
__global__ void qbias_kernel(const float* __restrict__ input1,
                             const float* __restrict__ Wq) {
    int b = blockIdx.x, n = threadIdx.x;
    const float* x = input1 + b * Ee;
    float acc = 0.f;
#pragma unroll 4
    for (int e = 0; e < Ee; e++) acc += x[e] * Wq[e * HK + n];
    g_c1[b * HK + n] = acc;
}

// ---------------------------------------------------------------------------
// Projections: z=0 K, z=1 V, z=2 Q (+c1 + t*wq_last). Heads layout out (fp32).
// ---------------------------------------------------------------------------
__global__ __launch_bounds__(256)
void proj_mma(const float* __restrict__ tvec, const float* __restrict__ wql) {
    extern __shared__ char smem[];
    const int z = blockIdx.z;
    const int m0 = blockIdx.x * 128, n0 = blockIdx.y * 128;
    const __nv_bfloat16* Ah = ((z == 2) ? i2_h : e_h) + (size_t)m0 * 256;
    const __nv_bfloat16* Al = ((z == 2) ? i2_l : e_l) + (size_t)m0 * 256;
    const __nv_bfloat16* Bh = ((z == 0) ? wkT_h : (z == 1) ? wvT_h : wqT_h) + (size_t)n0 * 256;
    const __nv_bfloat16* Bl = ((z == 0) ? wkT_l : (z == 1) ? wvT_l : wqT_l) + (size_t)n0 * 256;
    float* C = (z == 0) ? g_Kt : (z == 1) ? g_Vt : g_Qt;

    float acc[2][8][4];
#pragma unroll
    for (int i = 0; i < 2; i++)
#pragma unroll
        for (int j = 0; j < 8; j++)
#pragma unroll
            for (int k = 0; k < 4; k++) acc[i][j][k] = 0.f;

    mma_gemm_tile(Ah, Al, Bh, Bl, smem, acc);

    const int warp = threadIdx.x >> 5, lane = threadIdx.x & 31;
    const int wm = (warp >> 1) * 32, wn = (warp & 1) * 64;

#pragma unroll
    for (int mt = 0; mt < 2; mt++) {
#pragma unroll
        for (int half = 0; half < 2; half++) {
            int m = m0 + wm + mt * 16 + (lane >> 2) + half * 8;
            int b = m >> 9, r = m & 511;
            float t = (z == 2) ? tvec[m] : 0.f;
#pragma unroll
            for (int ng = 0; ng < 8; ng++) {
                int n = n0 + wn + ng * 8 + (lane & 3) * 2;
                float v0 = acc[mt][ng][half * 2];
                float v1 = acc[mt][ng][half * 2 + 1];
                if (z == 2) {
                    v0 += g_c1[b * HK + n] + t * wql[n];
                    v1 += g_c1[b * HK + n + 1] + t * wql[n + 1];
                }
                int h = n >> 4, kc = n & 15;
                *(float2*)&C[(((size_t)(b * Hh + h) * 512 + r) << 4) + kc] =
                    make_float2(v0, v1);
            }
        }
    }
}

// ---------------------------------------------------------------------------
__global__ __launch_bounds__(256)
void wc_mma(const float* __restrict__ bias) {
    extern __shared__ char smem[];
    const int m0 = blockIdx.x * 128, n0 = blockIdx.y * 128;

    float acc[2][8][4];
#pragma unroll
    for (int i = 0; i < 2; i++)
#pragma unroll
        for (int j = 0; j < 8; j++)
#pragma unroll
            for (int k = 0; k < 4; k++) acc[i][j][k] = 0.f;

    mma_gemm_tile(at_h + (size_t)m0 * 256, at_l + (size_t)m0 * 256,
                  wcT_h + (size_t)n0 * 256, wcT_l + (size_t)n0 * 256, smem, acc);

    const int warp = threadIdx.x >> 5, lane = threadIdx.x & 31;
    const int wm = (warp >> 1) * 32, wn = (warp & 1) * 64;

#pragma unroll
    for (int mt = 0; mt < 2; mt++) {
#pragma unroll
        for (int half = 0; half < 2; half++) {
            int m = m0 + wm + mt * 16 + (lane >> 2) + half * 8;
#pragma unroll
            for (int ng = 0; ng < 8; ng++) {
                int n = n0 + wn + ng * 8 + (lane & 3) * 2;
                float v0 = acc[mt][ng][half * 2] + bias[n];
                float v1 = acc[mt][ng][half * 2 + 1] + bias[n + 1];
                __nv_bfloat16 h0 = __float2bfloat16(v0);
                __nv_bfloat16 h1 = __float2bfloat16(v1);
                size_t idx = (size_t)m * 256 + n;
                *(__nv_bfloat162*)&mh_h[idx] = __nv_bfloat162(h0, h1);
                *(__nv_bfloat162*)&mh_l[idx] = __nv_bfloat162(
                    __float2bfloat16(v0 - __bfloat162float(h0)),
                    __float2bfloat16(v1 - __bfloat162float(h1)));
            }
        }
    }
}

// ---------------------------------------------------------------------------
__device__ __forceinline__ float fast_tanh10(float x) {
    x = fminf(fmaxf(x, -15.f), 15.f);
    float e = __expf(2.f * x);
    return 10.f * (1.f - __fdividef(2.f, e + 1.f));
}

__global__ __launch_bounds__(256)
void pointer_mma(const float* __restrict__ mask) {
    extern __shared__ char smem[];
    const int b = blockIdx.z;
    const int g0 = blockIdx.x * 128, p0 = blockIdx.y * 128;
    const size_t bo = (size_t)b * Gg * HK;

    float acc[2][8][4];
#pragma unroll
    for (int i = 0; i < 2; i++)
#pragma unroll
        for (int j = 0; j < 8; j++)
#pragma unroll
            for (int k = 0; k < 4; k++) acc[i][j][k] = 0.f;

    mma_gemm_tile(mh_h + bo + (size_t)g0 * 256, mh_l + bo + (size_t)g0 * 256,
                  e_h + bo + (size_t)p0 * 256, e_l + bo + (size_t)p0 * 256,
                  smem, acc);

    const int warp = threadIdx.x >> 5, lane = threadIdx.x & 31;
    const int wm = (warp >> 1) * 32, wn = (warp & 1) * 64;

#pragma unroll
    for (int mt = 0; mt < 2; mt++) {
#pragma unroll
        for (int half = 0; half < 2; half++) {
            int g = g0 + wm + mt * 16 + (lane >> 2) + half * 8;
#pragma unroll
            for (int ng = 0; ng < 8; ng++) {
                int p = p0 + wn + ng * 8 + (lane & 3) * 2;
                size_t idx = (size_t)(b * Gg + g) * Pp + p;
                float2 mk = *(const float2*)&mask[idx];
                *(float2*)&g_s2[idx] = make_float2(
                    fast_tanh10(acc[mt][ng][half * 2] * 0.0625f) + mk.x,
                    fast_tanh10(acc[mt][ng][half * 2 + 1] * 0.0625f) + mk.y);
            }
        }
    }
}

// ---------------------------------------------------------------------------
// Warp-autonomous attention (R8-proven). Output -> bf16 hi/lo split.
// ---------------------------------------------------------------------------
#define AT_STR 20
#define ATTN_SMEM_BYTES (2 * 512 * AT_STR * 4)

__global__ __launch_bounds__(256, 1)
void attn_kernel(const float* __restrict__ mask) {
    extern __shared__ float sm[];
    float* sK = sm;
    float* sV = sm + 512 * AT_STR;

    const int tid = threadIdx.x;
    const int gbase = blockIdx.x * 256;
    const int h = blockIdx.y, b = blockIdx.z;
    const float* Kb = g_Kt + (size_t)(b * Hh + h) * Pp * Kd;
    const float* Vb = g_Vt + (size_t)(b * Hh + h) * Pp * Kd;
    const float* Qb = g_Qt + (size_t)(b * Hh + h) * Gg * Kd;

    for (int i = tid; i < 2048; i += 256) {
        int p = i >> 2, c = (i & 3) * 4;
        *(float4*)&sK[p * AT_STR + c] = ((const float4*)Kb)[i];
        *(float4*)&sV[p * AT_STR + c] = ((const float4*)Vb)[i];
    }
    __syncthreads();

    const int warp = tid >> 5, lane = tid & 31;
    const int kcout = (((lane >> 4) & 1) << 3) | (((lane >> 3) & 1) << 2) |
                      (((lane >> 2) & 1) << 1) | ((lane >> 1) & 1);
    const float SC2 = 0.25f * L2E;

    for (int pass = 0; pass < 8; pass++) {
        const int g0 = gbase + warp * 32 + pass * 4;

        F4U q[4][4];
#pragma unroll
        for (int qq = 0; qq < 4; qq++) {
            const float4* Qp = (const float4*)(Qb + (size_t)(g0 + qq) * 16);
            q[qq][0].f = Qp[0]; q[qq][1].f = Qp[1];
            q[qq][2].f = Qp[2]; q[qq][3].f = Qp[3];
        }

        float mk[4][16];
#pragma unroll
        for (int qq = 0; qq < 4; qq++) {
            const float* mrow = mask + (size_t)(b * Gg + g0 + qq) * Pp + lane;
#pragma unroll
            for (int i = 0; i < 16; i++) mk[qq][i] = mrow[32 * i] * L2E;
        }

        float s[4][16];
#pragma unroll
        for (int i = 0; i < 16; i++) {
            const float* kr = &sK[(lane + 32 * i) * AT_STR];
            F4U k0, k1, k2, k3;
            k0.f = *(const float4*)kr;
            k1.f = *(const float4*)(kr + 4);
            k2.f = *(const float4*)(kr + 8);
            k3.f = *(const float4*)(kr + 12);
#pragma unroll
            for (int qq = 0; qq < 4; qq++) {
                ull a = 0ull;
                fma2(a, q[qq][0].u[0], k0.u[0]); fma2(a, q[qq][0].u[1], k0.u[1]);
                fma2(a, q[qq][1].u[0], k1.u[0]); fma2(a, q[qq][1].u[1], k1.u[1]);
                fma2(a, q[qq][2].u[0], k2.u[0]); fma2(a, q[qq][2].u[1], k2.u[1]);
                fma2(a, q[qq][3].u[0], k3.u[0]); fma2(a, q[qq][3].u[1], k3.u[1]);
                float2 f = unpack2(a);
                s[qq][i] = f.x + f.y;
            }
        }

        float inv[4];
#pragma unroll
        for (int qq = 0; qq < 4; qq++) {
#pragma unroll
            for (int i = 0; i < 16; i++)
                s[qq][i] = fmaf(s[qq][i], SC2, mk[qq][i]);
            float mx = s[qq][0];
#pragma unroll
            for (int i = 1; i < 16; i++) mx = fmaxf(mx, s[qq][i]);
#pragma unroll
            for (int o = 16; o > 0; o >>= 1)
                mx = fmaxf(mx, __shfl_xor_sync(0xffffffffu, mx, o));
            float sum = 0.f;
#pragma unroll
            for (int i = 0; i < 16; i++) {
                s[qq][i] = ex2f(s[qq][i] - mx);
                sum += s[qq][i];
            }
#pragma unroll
            for (int o = 16; o > 0; o >>= 1)
                sum += __shfl_xor_sync(0xffffffffu, sum, o);
            inv[qq] = __fdividef(1.f, sum);
        }

        ull acc[4][8];
#pragma unroll
        for (int qq = 0; qq < 4; qq++)
#pragma unroll
            for (int j = 0; j < 8; j++) acc[qq][j] = 0ull;

#pragma unroll
        for (int i = 0; i < 16; i++) {
            const float* vr = &sV[(lane + 32 * i) * AT_STR];
            F4U v0, v1, v2, v3;
            v0.f = *(const float4*)vr;
            v1.f = *(const float4*)(vr + 4);
            v2.f = *(const float4*)(vr + 8);
            v3.f = *(const float4*)(vr + 12);
#pragma unroll
            for (int qq = 0; qq < 4; qq++) {
                ull wd = dup2(s[qq][i]);
                fma2(acc[qq][0], wd, v0.u[0]); fma2(acc[qq][1], wd, v0.u[1]);
                fma2(acc[qq][2], wd, v1.u[0]); fma2(acc[qq][3], wd, v1.u[1]);
                fma2(acc[qq][4], wd, v2.u[0]); fma2(acc[qq][5], wd, v2.u[1]);
                fma2(acc[qq][6], wd, v3.u[0]); fma2(acc[qq][7], wd, v3.u[1]);
            }
        }

#pragma unroll
        for (int qq = 0; qq < 4; qq++) {
            const ull ivd = dup2(inv[qq]);
            ull a8[8];
#pragma unroll
            for (int j = 0; j < 8; j++) a8[j] = mul2(acc[qq][j], ivd);

            ull n4[4];
#pragma unroll
            for (int j = 0; j < 4; j++) {
                ull snd = (lane & 16) ? a8[j] : a8[j + 4];
                ull kp  = (lane & 16) ? a8[j + 4] : a8[j];
                n4[j] = add2(kp, __shfl_xor_sync(0xffffffffu, snd, 16));
            }
            ull n2[2];
#pragma unroll
            for (int j = 0; j < 2; j++) {
                ull snd = (lane & 8) ? n4[j] : n4[j + 2];
                ull kp  = (lane & 8) ? n4[j + 2] : n4[j];
                n2[j] = add2(kp, __shfl_xor_sync(0xffffffffu, snd, 8));
            }
            ull n1;
            {
                ull snd = (lane & 4) ? n2[0] : n2[1];
                ull kp  = (lane & 4) ? n2[1] : n2[0];
                n1 = add2(kp, __shfl_xor_sync(0xffffffffu, snd, 4));
            }
            float2 t = unpack2(n1);
            float fs = (lane & 2) ? t.x : t.y;
            float fk = (lane & 2) ? t.y : t.x;
            float f = fk + __shfl_xor_sync(0xffffffffu, fs, 2);
            f += __shfl_xor_sync(0xffffffffu, f, 1);

            if (!(lane & 1)) {
                size_t idx = (size_t)(b * Gg + g0 + qq) * HK + h * 16 + kcout;
                __nv_bfloat16 hb = __float2bfloat16(f);
                at_h[idx] = hb;
                at_l[idx] = __float2bfloat16(f - __bfloat162float(hb));
            }
        }
    }
}

// ---------------------------------------------------------------------------
// Row softmax over P=512 (no max pass: scores bounded above by 10).
// ---------------------------------------------------------------------------
__global__ __launch_bounds__(256)
void softmax_kernel(float* __restrict__ out) {
    __shared__ float sred[8];
    __shared__ float sinv;
    const int row = blockIdx.x;
    const int tid = threadIdx.x;
    const float* in = g_s2 + (size_t)row * Pp;

    float v0 = in[tid], v1 = in[tid + 256];
    float e0 = ex2f(fmaf(v0, L2E, -10.f * L2E));
    float e1 = ex2f(fmaf(v1, L2E, -10.f * L2E));
    float lsum = e0 + e1;
#pragma unroll
    for (int o = 16; o > 0; o >>= 1)
        lsum += __shfl_xor_sync(0xffffffffu, lsum, o);
    if ((tid & 31) == 0) sred[tid >> 5] = lsum;
    __syncthreads();
    if (tid == 0) {
        float s = 0.f;
#pragma unroll
        for (int w = 0; w < 8; w++) s += sred[w];
        sinv = 1.f / s;
    }
    __syncthreads();
    float inv = sinv;
    out[(size_t)row * Pp + tid] = e0 * inv;
    out[(size_t)row * Pp + tid + 256] = e1 * inv;
}

// ---------------------------------------------------------------------------
extern "C" void kernel_launch(void* const* d_in, const int* in_sizes, int n_in,
                              void* d_out, int out_size) {
    const float* input1 = (const float*)d_in[0];
    const float* input2 = (const float*)d_in[1];
    const float* ctime  = (const float*)d_in[2];
    const float* mask   = (const float*)d_in[3];
    const float* enc    = (const float*)d_in[4];
    const float* Wq     = (const float*)d_in[5];
    const float* Wk     = (const float*)d_in[6];
    const float* Wv     = (const float*)d_in[7];
    const float* Wcw    = (const float*)d_in[8];
    const float* Wcb    = (const float*)d_in[9];
    float* out = (float*)d_out;

    __nv_bfloat16 *pEh, *pEl, *pI2h, *pI2l;
    __nv_bfloat16 *pWkh, *pWkl, *pWvh, *pWvl, *pWqh, *pWql2, *pWch, *pWcl;
    cudaGetSymbolAddress((void**)&pEh, e_h);
    cudaGetSymbolAddress((void**)&pEl, e_l);
    cudaGetSymbolAddress((void**)&pI2h, i2_h);
    cudaGetSymbolAddress((void**)&pI2l, i2_l);
    cudaGetSymbolAddress((void**)&pWkh, wkT_h);
    cudaGetSymbolAddress((void**)&pWkl, wkT_l);
    cudaGetSymbolAddress((void**)&pWvh, wvT_h);
    cudaGetSymbolAddress((void**)&pWvl, wvT_l);
    cudaGetSymbolAddress((void**)&pWqh, wqT_h);
    cudaGetSymbolAddress((void**)&pWql2, wqT_l);
    cudaGetSymbolAddress((void**)&pWch, wcT_h);
    cudaGetSymbolAddress((void**)&pWcl, wcT_l);

    // operand splits
    split_kernel<<<NBIG / 256, 256>>>(enc, pEh, pEl, NBIG);
    split_kernel<<<NBIG / 256, 256>>>(input2, pI2h, pI2l, NBIG);
    wsplit_kernel<<<256, 256>>>(Wk, pWkh, pWkl);
    wsplit_kernel<<<256, 256>>>(Wv, pWvh, pWvl);
    wsplit_kernel<<<256, 256>>>(Wq + Ee * HK, pWqh, pWql2);
    wsplit_kernel<<<256, 256>>>(Wcw, pWch, pWcl);

    qbias_kernel<<<Bb, 256>>>(input1, Wq);

    cudaFuncSetAttribute(proj_mma, cudaFuncAttributeMaxDynamicSharedMemorySize, MMA_SMEM_BYTES);
    cudaFuncSetAttribute(wc_mma, cudaFuncAttributeMaxDynamicSharedMemorySize, MMA_SMEM_BYTES);
    cudaFuncSetAttribute(pointer_mma, cudaFuncAttributeMaxDynamicSharedMemorySize, MMA_SMEM_BYTES);
    cudaFuncSetAttribute(attn_kernel, cudaFuncAttributeMaxDynamicSharedMemorySize, ATTN_SMEM_BYTES);

    proj_mma<<<dim3(64, 2, 3), 256, MMA_SMEM_BYTES>>>(ctime, Wq + 2 * Ee * HK);

    attn_kernel<<<dim3(2, Hh, Bb), 256, ATTN_SMEM_BYTES>>>(mask);

    wc_mma<<<dim3(64, 2), 256, MMA_SMEM_BYTES>>>(Wcb);

    pointer_mma<<<dim3(4, 4, Bb), 256, MMA_SMEM_BYTES>>>(mask);

    softmax_kernel<<<Bb * Gg, 256>>>(out);
}

// round 11
// speedup vs baseline: 1.4705x; 1.0379x over previous
#include <cuda_runtime.h>
#include <cuda_bf16.h>
#include <math.h>
#include <cstdint>

#define Bb 16
#define Gg 512
#define Pp 512
#define Ee 256
#define Hh 16
#define Kd 16
#define HK 256

typedef unsigned long long ull;

// ---------------- device globals (allocation-free rule) ----------------
__device__ float g_c1[Bb * HK];
__device__ float g_Kt[Bb * Hh * Pp * Kd];
__device__ float g_Vt[Bb * Hh * Pp * Kd];
__device__ float g_Qt[Bb * Hh * Gg * Kd];
__device__ float g_s2[Bb * Gg * Pp];

#define NBIG (Bb * Gg * HK)   // 2097152
__device__ __nv_bfloat16 e_h[NBIG],  e_l[NBIG];
__device__ __nv_bfloat16 i2_h[NBIG], i2_l[NBIG];
__device__ __nv_bfloat16 at_h[NBIG], at_l[NBIG];
__device__ __nv_bfloat16 mh_h[NBIG], mh_l[NBIG];
__device__ __nv_bfloat16 wkT_h[HK * HK], wkT_l[HK * HK];
__device__ __nv_bfloat16 wvT_h[HK * HK], wvT_l[HK * HK];
__device__ __nv_bfloat16 wqT_h[HK * HK], wqT_l[HK * HK];
__device__ __nv_bfloat16 wcT_h[HK * HK], wcT_l[HK * HK];

// ---------------- packed f32x2 helpers (attention) ----------------
__device__ __forceinline__ ull dup2(float a) {
    ull r; asm("mov.b64 %0, {%1, %1};" : "=l"(r) : "f"(a)); return r;
}
__device__ __forceinline__ void fma2(ull& d, ull a, ull b) {
    asm("fma.rn.f32x2 %0, %1, %2, %3;" : "=l"(d) : "l"(a), "l"(b), "l"(d));
}
__device__ __forceinline__ float2 unpack2(ull v) {
    float2 f; asm("mov.b64 {%0, %1}, %2;" : "=f"(f.x), "=f"(f.y) : "l"(v)); return f;
}
__device__ __forceinline__ ull add2(ull a, ull b) {
    ull r; asm("add.rn.f32x2 %0, %1, %2;" : "=l"(r) : "l"(a), "l"(b)); return r;
}
__device__ __forceinline__ ull mul2(ull a, ull b) {
    ull r; asm("mul.rn.f32x2 %0, %1, %2;" : "=l"(r) : "l"(a), "l"(b)); return r;
}
__device__ __forceinline__ float ex2f(float x) {
    float r; asm("ex2.approx.f32 %0, %1;" : "=f"(r) : "f"(x)); return r;
}
#define L2E 1.44269504089f
union F4U { float4 f; ull u[2]; };

// ---------------- mma.sync + cp.async helpers ----------------
__device__ __forceinline__ uint32_t smem_u32(const void* p) {
    uint32_t a;
    asm("{ .reg .u64 t; cvta.to.shared.u64 t, %1; cvt.u32.u64 %0, t; }" : "=r"(a) : "l"(p));
    return a;
}
__device__ __forceinline__ void ldm_x4(uint32_t* r, uint32_t addr) {
    asm volatile("ldmatrix.sync.aligned.m8n8.x4.shared.b16 {%0,%1,%2,%3}, [%4];"
                 : "=r"(r[0]), "=r"(r[1]), "=r"(r[2]), "=r"(r[3]) : "r"(addr));
}
__device__ __forceinline__ void mma_bf16(float* d, const uint32_t* a, const uint32_t* b) {
    asm volatile("mma.sync.aligned.m16n8k16.row.col.f32.bf16.bf16.f32 "
                 "{%0,%1,%2,%3}, {%4,%5,%6,%7}, {%8,%9}, {%0,%1,%2,%3};"
                 : "+f"(d[0]), "+f"(d[1]), "+f"(d[2]), "+f"(d[3])
                 : "r"(a[0]), "r"(a[1]), "r"(a[2]), "r"(a[3]), "r"(b[0]), "r"(b[1]));
}
__device__ __forceinline__ void cp_async16(uint32_t saddr, const void* g) {
    asm volatile("cp.async.cg.shared.global [%0], [%1], 16;" :: "r"(saddr), "l"(g));
}
#define CP_COMMIT() asm volatile("cp.async.commit_group;" ::: "memory")
#define CP_WAIT0()  asm volatile("cp.async.wait_group 0;" ::: "memory")

// SMEM: 4 tiles of 128 rows x 144B per buffer, double buffered
#define ROWB 144
#define T_AH 0u
#define T_AL 18432u
#define T_BH 36864u
#define T_BL 55296u
#define BUFSZ 73728u
#define MMA_SMEM_BYTES (2 * 73728)

// ---------------------------------------------------------------------------
// Core: acc[2][8][4] += (Ah+Al)[128x256] . (Bh+Bl)[128x256]^T  (both K-major)
// 256 threads, 8 warps 4(M) x 2(N), warp tile 32x64, K in 4 chunks,
// cp.async double-buffered staging.
// ---------------------------------------------------------------------------
__device__ __forceinline__ void mma_gemm_tile(
    const __nv_bfloat16* __restrict__ Ah, const __nv_bfloat16* __restrict__ Al,
    const __nv_bfloat16* __restrict__ Bh, const __nv_bfloat16* __restrict__ Bl,
    char* smem, float acc[2][8][4])
{
    const int tid = threadIdx.x;
    const int warp = tid >> 5, lane = tid & 31;
    const int wm = (warp >> 1) * 32;
    const int wn = (warp & 1) * 64;
    const uint32_t sb = smem_u32(smem);

    const int a_r = lane & 15;
    const int a_kh = ((lane >> 4) & 1) << 3;
    const int b_r = (lane & 7) + (((lane >> 4) & 1) << 3);
    const int b_kh = ((lane >> 3) & 1) << 3;

    const __nv_bfloat16* srcs[4] = {Ah, Al, Bh, Bl};
    const uint32_t offs[4] = {T_AH, T_AL, T_BH, T_BL};
    const int st_r = tid >> 3, st_c = tid & 7;   // staging row/col16

    // stage chunk 0 into buffer 0
#pragma unroll
    for (int a = 0; a < 4; a++) {
        const uint4* s = (const uint4*)(srcs[a]);
#pragma unroll
        for (int i = 0; i < 4; i++) {
            int r = st_r + (i << 5);
            cp_async16(sb + offs[a] + (uint32_t)(r * ROWB + st_c * 16),
                       s + r * 32 + st_c);
        }
    }
    CP_COMMIT();
    CP_WAIT0();
    __syncthreads();

    for (int c = 0; c < 4; c++) {
        const uint32_t bbase = (uint32_t)(c & 1) * BUFSZ;

        // prefetch chunk c+1 into the other buffer
        if (c < 3) {
            const uint32_t nbase = (uint32_t)((c + 1) & 1) * BUFSZ;
            const int k0 = (c + 1) * 64;
#pragma unroll
            for (int a = 0; a < 4; a++) {
                const uint4* s = (const uint4*)(srcs[a] + k0);
#pragma unroll
                for (int i = 0; i < 4; i++) {
                    int r = st_r + (i << 5);
                    cp_async16(sb + nbase + offs[a] + (uint32_t)(r * ROWB + st_c * 16),
                               s + r * 32 + st_c);
                }
            }
            CP_COMMIT();
        }

        // compute chunk c from bbase
#pragma unroll
        for (int ks = 0; ks < 4; ks++) {
            const int kb = ks * 32;

            uint32_t af[2][4];
#pragma unroll
            for (int mt = 0; mt < 2; mt++)
                ldm_x4(af[mt], sb + bbase + T_AH +
                       (uint32_t)((wm + mt * 16 + a_r) * ROWB + kb + a_kh * 2));

            uint32_t bh[4][4], bl[4][4];
#pragma unroll
            for (int ng = 0; ng < 4; ng++) {
                uint32_t ro = (uint32_t)((wn + ng * 16 + b_r) * ROWB + kb + b_kh * 2);
                ldm_x4(bh[ng], sb + bbase + T_BH + ro);
                ldm_x4(bl[ng], sb + bbase + T_BL + ro);
            }

#pragma unroll
            for (int mt = 0; mt < 2; mt++)
#pragma unroll
                for (int ng = 0; ng < 4; ng++) {
                    mma_bf16(acc[mt][ng * 2],     af[mt], &bh[ng][0]);
                    mma_bf16(acc[mt][ng * 2 + 1], af[mt], &bh[ng][2]);
                    mma_bf16(acc[mt][ng * 2],     af[mt], &bl[ng][0]);
                    mma_bf16(acc[mt][ng * 2 + 1], af[mt], &bl[ng][2]);
                }

#pragma unroll
            for (int mt = 0; mt < 2; mt++)
                ldm_x4(af[mt], sb + bbase + T_AL +
                       (uint32_t)((wm + mt * 16 + a_r) * ROWB + kb + a_kh * 2));
#pragma unroll
            for (int mt = 0; mt < 2; mt++)
#pragma unroll
                for (int ng = 0; ng < 4; ng++) {
                    mma_bf16(acc[mt][ng * 2],     af[mt], &bh[ng][0]);
                    mma_bf16(acc[mt][ng * 2 + 1], af[mt], &bh[ng][2]);
                }
        }

        if (c < 3) {
            CP_WAIT0();
            __syncthreads();
        }
    }
}

// ---------------------------------------------------------------------------
// conversion kernels (merged)
// ---------------------------------------------------------------------------
__global__ void split_all(const float* __restrict__ enc,
                          const float* __restrict__ inp2) {
    int i = blockIdx.x * 256 + threadIdx.x;
    const float* src = blockIdx.y ? inp2 : enc;
    __nv_bfloat16* h = blockIdx.y ? i2_h : e_h;
    __nv_bfloat16* l = blockIdx.y ? i2_l : e_l;
    float x = src[i];
    __nv_bfloat16 hb = __float2bfloat16(x);
    h[i] = hb;
    l[i] = __float2bfloat16(x - __bfloat162float(hb));
}

__global__ void wsplit_all(const float* __restrict__ Wk,
                           const float* __restrict__ Wv,
                           const float* __restrict__ Wqm,
                           const float* __restrict__ Wc) {
    int k = blockIdx.x, n = threadIdx.x;
    int z = blockIdx.y;
    const float* W = (z == 0) ? Wk : (z == 1) ? Wv : (z == 2) ? Wqm : Wc;
    __nv_bfloat16* th = (z == 0) ? wkT_h : (z == 1) ? wvT_h : (z == 2) ? wqT_h : wcT_h;
    __nv_bfloat16* tl = (z == 0) ? wkT_l : (z == 1) ? wvT_l : (z == 2) ? wqT_l : wcT_l;
    float x = W[k * 256 + n];
    __nv_bfloat16 hb = __float2bfloat16(x);
    th[n * 256 + k] = hb;
    tl[n * 256 + k] = __float2bfloat16(x - __bfloat162float(hb));
}

// ---------------------------------------------------------------------------
__global__ void qbias_kernel(const float* __restrict__ input1,
                             const float* __restrict__ Wq) {
    int b = blockIdx.x, n = threadIdx.x;
    const float* x = input1 + b * Ee;
    float acc = 0.f;
#pragma unroll 4
    for (int e = 0; e < Ee; e++) acc += x[e] * Wq[e * HK + n];
    g_c1[b * HK + n] = acc;
}

// ---------------------------------------------------------------------------
// Projections: z=0 K, z=1 V, z=2 Q (+c1 + t*wq_last). Heads layout out (fp32).
// ---------------------------------------------------------------------------
__global__ __launch_bounds__(256)
void proj_mma(const float* __restrict__ tvec, const float* __restrict__ wql) {
    extern __shared__ char smem[];
    const int z = blockIdx.z;
    const int m0 = blockIdx.x * 128, n0 = blockIdx.y * 128;
    const __nv_bfloat16* Ah = ((z == 2) ? i2_h : e_h) + (size_t)m0 * 256;
    const __nv_bfloat16* Al = ((z == 2) ? i2_l : e_l) + (size_t)m0 * 256;
    const __nv_bfloat16* Bh = ((z == 0) ? wkT_h : (z == 1) ? wvT_h : wqT_h) + (size_t)n0 * 256;
    const __nv_bfloat16* Bl = ((z == 0) ? wkT_l : (z == 1) ? wvT_l : wqT_l) + (size_t)n0 * 256;
    float* C = (z == 0) ? g_Kt : (z == 1) ? g_Vt : g_Qt;

    float acc[2][8][4];
#pragma unroll
    for (int i = 0; i < 2; i++)
#pragma unroll
        for (int j = 0; j < 8; j++)
#pragma unroll
            for (int k = 0; k < 4; k++) acc[i][j][k] = 0.f;

    mma_gemm_tile(Ah, Al, Bh, Bl, smem, acc);

    const int warp = threadIdx.x >> 5, lane = threadIdx.x & 31;
    const int wm = (warp >> 1) * 32, wn = (warp & 1) * 64;

#pragma unroll
    for (int mt = 0; mt < 2; mt++) {
#pragma unroll
        for (int half = 0; half < 2; half++) {
            int m = m0 + wm + mt * 16 + (lane >> 2) + half * 8;
            int b = m >> 9, r = m & 511;
            float t = (z == 2) ? tvec[m] : 0.f;
#pragma unroll
            for (int ng = 0; ng < 8; ng++) {
                int n = n0 + wn + ng * 8 + (lane & 3) * 2;
                float v0 = acc[mt][ng][half * 2];
                float v1 = acc[mt][ng][half * 2 + 1];
                if (z == 2) {
                    v0 += g_c1[b * HK + n] + t * wql[n];
                    v1 += g_c1[b * HK + n + 1] + t * wql[n + 1];
                }
                int h = n >> 4, kc = n & 15;
                *(float2*)&C[(((size_t)(b * Hh + h) * 512 + r) << 4) + kc] =
                    make_float2(v0, v1);
            }
        }
    }
}

// ---------------------------------------------------------------------------
__global__ __launch_bounds__(256)
void wc_mma(const float* __restrict__ bias) {
    extern __shared__ char smem[];
    const int m0 = blockIdx.x * 128, n0 = blockIdx.y * 128;

    float acc[2][8][4];
#pragma unroll
    for (int i = 0; i < 2; i++)
#pragma unroll
        for (int j = 0; j < 8; j++)
#pragma unroll
            for (int k = 0; k < 4; k++) acc[i][j][k] = 0.f;

    mma_gemm_tile(at_h + (size_t)m0 * 256, at_l + (size_t)m0 * 256,
                  wcT_h + (size_t)n0 * 256, wcT_l + (size_t)n0 * 256, smem, acc);

    const int warp = threadIdx.x >> 5, lane = threadIdx.x & 31;
    const int wm = (warp >> 1) * 32, wn = (warp & 1) * 64;

#pragma unroll
    for (int mt = 0; mt < 2; mt++) {
#pragma unroll
        for (int half = 0; half < 2; half++) {
            int m = m0 + wm + mt * 16 + (lane >> 2) + half * 8;
#pragma unroll
            for (int ng = 0; ng < 8; ng++) {
                int n = n0 + wn + ng * 8 + (lane & 3) * 2;
                float v0 = acc[mt][ng][half * 2] + bias[n];
                float v1 = acc[mt][ng][half * 2 + 1] + bias[n + 1];
                __nv_bfloat16 h0 = __float2bfloat16(v0);
                __nv_bfloat16 h1 = __float2bfloat16(v1);
                size_t idx = (size_t)m * 256 + n;
                *(__nv_bfloat162*)&mh_h[idx] = __nv_bfloat162(h0, h1);
                *(__nv_bfloat162*)&mh_l[idx] = __nv_bfloat162(
                    __float2bfloat16(v0 - __bfloat162float(h0)),
                    __float2bfloat16(v1 - __bfloat162float(h1)));
            }
        }
    }
}

// ---------------------------------------------------------------------------
__device__ __forceinline__ float fast_tanh10(float x) {
    x = fminf(fmaxf(x, -15.f), 15.f);
    float e = __expf(2.f * x);
    return 10.f * (1.f - __fdividef(2.f, e + 1.f));
}

__global__ __launch_bounds__(256)
void pointer_mma(const float* __restrict__ mask) {
    extern __shared__ char smem[];
    const int b = blockIdx.z;
    const int g0 = blockIdx.x * 128, p0 = blockIdx.y * 128;
    const size_t bo = (size_t)b * Gg * HK;

    float acc[2][8][4];
#pragma unroll
    for (int i = 0; i < 2; i++)
#pragma unroll
        for (int j = 0; j < 8; j++)
#pragma unroll
            for (int k = 0; k < 4; k++) acc[i][j][k] = 0.f;

    mma_gemm_tile(mh_h + bo + (size_t)g0 * 256, mh_l + bo + (size_t)g0 * 256,
                  e_h + bo + (size_t)p0 * 256, e_l + bo + (size_t)p0 * 256,
                  smem, acc);

    const int warp = threadIdx.x >> 5, lane = threadIdx.x & 31;
    const int wm = (warp >> 1) * 32, wn = (warp & 1) * 64;

#pragma unroll
    for (int mt = 0; mt < 2; mt++) {
#pragma unroll
        for (int half = 0; half < 2; half++) {
            int g = g0 + wm + mt * 16 + (lane >> 2) + half * 8;
#pragma unroll
            for (int ng = 0; ng < 8; ng++) {
                int p = p0 + wn + ng * 8 + (lane & 3) * 2;
                size_t idx = (size_t)(b * Gg + g) * Pp + p;
                float2 mk = *(const float2*)&mask[idx];
                *(float2*)&g_s2[idx] = make_float2(
                    fast_tanh10(acc[mt][ng][half * 2] * 0.0625f) + mk.x,
                    fast_tanh10(acc[mt][ng][half * 2 + 1] * 0.0625f) + mk.y);
            }
        }
    }
}

// ---------------------------------------------------------------------------
// Warp-autonomous attention (R8-proven). Output -> bf16 hi/lo split.
// ---------------------------------------------------------------------------
#define AT_STR 20
#define ATTN_SMEM_BYTES (2 * 512 * AT_STR * 4)

__global__ __launch_bounds__(256, 1)
void attn_kernel(const float* __restrict__ mask) {
    extern __shared__ float sm[];
    float* sK = sm;
    float* sV = sm + 512 * AT_STR;

    const int tid = threadIdx.x;
    const int gbase = blockIdx.x * 256;
    const int h = blockIdx.y, b = blockIdx.z;
    const float* Kb = g_Kt + (size_t)(b * Hh + h) * Pp * Kd;
    const float* Vb = g_Vt + (size_t)(b * Hh + h) * Pp * Kd;
    const float* Qb = g_Qt + (size_t)(b * Hh + h) * Gg * Kd;

    for (int i = tid; i < 2048; i += 256) {
        int p = i >> 2, c = (i & 3) * 4;
        *(float4*)&sK[p * AT_STR + c] = ((const float4*)Kb)[i];
        *(float4*)&sV[p * AT_STR + c] = ((const float4*)Vb)[i];
    }
    __syncthreads();

    const int warp = tid >> 5, lane = tid & 31;
    const int kcout = (((lane >> 4) & 1) << 3) | (((lane >> 3) & 1) << 2) |
                      (((lane >> 2) & 1) << 1) | ((lane >> 1) & 1);
    const float SC2 = 0.25f * L2E;

    for (int pass = 0; pass < 8; pass++) {
        const int g0 = gbase + warp * 32 + pass * 4;

        F4U q[4][4];
#pragma unroll
        for (int qq = 0; qq < 4; qq++) {
            const float4* Qp = (const float4*)(Qb + (size_t)(g0 + qq) * 16);
            q[qq][0].f = Qp[0]; q[qq][1].f = Qp[1];
            q[qq][2].f = Qp[2]; q[qq][3].f = Qp[3];
        }

        float mk[4][16];
#pragma unroll
        for (int qq = 0; qq < 4; qq++) {
            const float* mrow = mask + (size_t)(b * Gg + g0 + qq) * Pp + lane;
#pragma unroll
            for (int i = 0; i < 16; i++) mk[qq][i] = mrow[32 * i] * L2E;
        }

        float s[4][16];
#pragma unroll
        for (int i = 0; i < 16; i++) {
            const float* kr = &sK[(lane + 32 * i) * AT_STR];
            F4U k0, k1, k2, k3;
            k0.f = *(const float4*)kr;
            k1.f = *(const float4*)(kr + 4);
            k2.f = *(const float4*)(kr + 8);
            k3.f = *(const float4*)(kr + 12);
#pragma unroll
            for (int qq = 0; qq < 4; qq++) {
                ull a = 0ull;
                fma2(a, q[qq][0].u[0], k0.u[0]); fma2(a, q[qq][0].u[1], k0.u[1]);
                fma2(a, q[qq][1].u[0], k1.u[0]); fma2(a, q[qq][1].u[1], k1.u[1]);
                fma2(a, q[qq][2].u[0], k2.u[0]); fma2(a, q[qq][2].u[1], k2.u[1]);
                fma2(a, q[qq][3].u[0], k3.u[0]); fma2(a, q[qq][3].u[1], k3.u[1]);
                float2 f = unpack2(a);
                s[qq][i] = f.x + f.y;
            }
        }

        float inv[4];
#pragma unroll
        for (int qq = 0; qq < 4; qq++) {
#pragma unroll
            for (int i = 0; i < 16; i++)
                s[qq][i] = fmaf(s[qq][i], SC2, mk[qq][i]);
            float mx = s[qq][0];
#pragma unroll
            for (int i = 1; i < 16; i++) mx = fmaxf(mx, s[qq][i]);
#pragma unroll
            for (int o = 16; o > 0; o >>= 1)
                mx = fmaxf(mx, __shfl_xor_sync(0xffffffffu, mx, o));
            float sum = 0.f;
#pragma unroll
            for (int i = 0; i < 16; i++) {
                s[qq][i] = ex2f(s[qq][i] - mx);
                sum += s[qq][i];
            }
#pragma unroll
            for (int o = 16; o > 0; o >>= 1)
                sum += __shfl_xor_sync(0xffffffffu, sum, o);
            inv[qq] = __fdividef(1.f, sum);
        }

        ull acc[4][8];
#pragma unroll
        for (int qq = 0; qq < 4; qq++)
#pragma unroll
            for (int j = 0; j < 8; j++) acc[qq][j] = 0ull;

#pragma unroll
        for (int i = 0; i < 16; i++) {
            const float* vr = &sV[(lane + 32 * i) * AT_STR];
            F4U v0, v1, v2, v3;
            v0.f = *(const float4*)vr;
            v1.f = *(const float4*)(vr + 4);
            v2.f = *(const float4*)(vr + 8);
            v3.f = *(const float4*)(vr + 12);
#pragma unroll
            for (int qq = 0; qq < 4; qq++) {
                ull wd = dup2(s[qq][i]);
                fma2(acc[qq][0], wd, v0.u[0]); fma2(acc[qq][1], wd, v0.u[1]);
                fma2(acc[qq][2], wd, v1.u[0]); fma2(acc[qq][3], wd, v1.u[1]);
                fma2(acc[qq][4], wd, v2.u[0]); fma2(acc[qq][5], wd, v2.u[1]);
                fma2(acc[qq][6], wd, v3.u[0]); fma2(acc[qq][7], wd, v3.u[1]);
            }
        }

#pragma unroll
        for (int qq = 0; qq < 4; qq++) {
            const ull ivd = dup2(inv[qq]);
            ull a8[8];
#pragma unroll
            for (int j = 0; j < 8; j++) a8[j] = mul2(acc[qq][j], ivd);

            ull n4[4];
#pragma unroll
            for (int j = 0; j < 4; j++) {
                ull snd = (lane & 16) ? a8[j] : a8[j + 4];
                ull kp  = (lane & 16) ? a8[j + 4] : a8[j];
                n4[j] = add2(kp, __shfl_xor_sync(0xffffffffu, snd, 16));
            }
            ull n2[2];
#pragma unroll
            for (int j = 0; j < 2; j++) {
                ull snd = (lane & 8) ? n4[j] : n4[j + 2];
                ull kp  = (lane & 8) ? n4[j + 2] : n4[j];
                n2[j] = add2(kp, __shfl_xor_sync(0xffffffffu, snd, 8));
            }
            ull n1;
            {
                ull snd = (lane & 4) ? n2[0] : n2[1];
                ull kp  = (lane & 4) ? n2[1] : n2[0];
                n1 = add2(kp, __shfl_xor_sync(0xffffffffu, snd, 4));
            }
            float2 t = unpack2(n1);
            float fs = (lane & 2) ? t.x : t.y;
            float fk = (lane & 2) ? t.y : t.x;
            float f = fk + __shfl_xor_sync(0xffffffffu, fs, 2);
            f += __shfl_xor_sync(0xffffffffu, f, 1);

            if (!(lane & 1)) {
                size_t idx = (size_t)(b * Gg + g0 + qq) * HK + h * 16 + kcout;
                __nv_bfloat16 hb = __float2bfloat16(f);
                at_h[idx] = hb;
                at_l[idx] = __float2bfloat16(f - __bfloat162float(hb));
            }
        }
    }
}

// ---------------------------------------------------------------------------
// Row softmax over P=512 (no max pass: scores bounded above by 10).
// ---------------------------------------------------------------------------
__global__ __launch_bounds__(256)
void softmax_kernel(float* __restrict__ out) {
    __shared__ float sred[8];
    __shared__ float sinv;
    const int row = blockIdx.x;
    const int tid = threadIdx.x;
    const float* in = g_s2 + (size_t)row * Pp;

    float v0 = in[tid], v1 = in[tid + 256];
    float e0 = ex2f(fmaf(v0, L2E, -10.f * L2E));
    float e1 = ex2f(fmaf(v1, L2E, -10.f * L2E));
    float lsum = e0 + e1;
#pragma unroll
    for (int o = 16; o > 0; o >>= 1)
        lsum += __shfl_xor_sync(0xffffffffu, lsum, o);
    if ((tid & 31) == 0) sred[tid >> 5] = lsum;
    __syncthreads();
    if (tid == 0) {
        float s = 0.f;
#pragma unroll
        for (int w = 0; w < 8; w++) s += sred[w];
        sinv = 1.f / s;
    }
    __syncthreads();
    float inv = sinv;
    out[(size_t)row * Pp + tid] = e0 * inv;
    out[(size_t)row * Pp + tid + 256] = e1 * inv;
}

// ---------------------------------------------------------------------------
extern "C" void kernel_launch(void* const* d_in, const int* in_sizes, int n_in,
                              void* d_out, int out_size) {
    const float* input1 = (const float*)d_in[0];
    const float* input2 = (const float*)d_in[1];
    const float* ctime  = (const float*)d_in[2];
    const float* mask   = (const float*)d_in[3];
    const float* enc    = (const float*)d_in[4];
    const float* Wq     = (const float*)d_in[5];
    const float* Wk     = (const float*)d_in[6];
    const float* Wv     = (const float*)d_in[7];
    const float* Wcw    = (const float*)d_in[8];
    const float* Wcb    = (const float*)d_in[9];
    float* out = (float*)d_out;

    split_all<<<dim3(NBIG / 256, 2), 256>>>(enc, input2);
    wsplit_all<<<dim3(256, 4), 256>>>(Wk, Wv, Wq + Ee * HK, Wcw);
    qbias_kernel<<<Bb, 256>>>(input1, Wq);

    cudaFuncSetAttribute(proj_mma, cudaFuncAttributeMaxDynamicSharedMemorySize, MMA_SMEM_BYTES);
    cudaFuncSetAttribute(wc_mma, cudaFuncAttributeMaxDynamicSharedMemorySize, MMA_SMEM_BYTES);
    cudaFuncSetAttribute(pointer_mma, cudaFuncAttributeMaxDynamicSharedMemorySize, MMA_SMEM_BYTES);
    cudaFuncSetAttribute(attn_kernel, cudaFuncAttributeMaxDynamicSharedMemorySize, ATTN_SMEM_BYTES);

    proj_mma<<<dim3(64, 2, 3), 256, MMA_SMEM_BYTES>>>(ctime, Wq + 2 * Ee * HK);

    attn_kernel<<<dim3(2, Hh, Bb), 256, ATTN_SMEM_BYTES>>>(mask);

    wc_mma<<<dim3(64, 2), 256, MMA_SMEM_BYTES>>>(Wcb);

    pointer_mma<<<dim3(4, 4, Bb), 256, MMA_SMEM_BYTES>>>(mask);

    softmax_kernel<<<Bb * Gg, 256>>>(out);
}